// round 1
// baseline (speedup 1.0000x reference)
#include <cuda_runtime.h>

// MPNN fused kernel: per CTA = 4 nodes = 64 edges.
//   edge MLP (384->128->128->128 + LN) -> block-local segmented sum -> node MLP (+ LN)
// All intermediates live in shared memory; no scratch, no atomics.

#define Dm        128
#define KDEG      16
#define NPB       4          // nodes per block
#define EPB       64         // edges per block (NPB*KDEG)
#define NTHREADS  256
#define HP        130        // padded row stride for activation buffers (bank spread)

// shared layout (floats):
//  sHa[64*130] | sHb[64*130] | sW[16*128] | sA[64*17] | sRed[256] | sRedSq[256]
//  sMu[64] | sRs[64] | sNin[512] | sNx[512] | sEg[128] | sEb[128]
#define SMEM_FLOATS (2*EPB*HP + 16*128 + EPB*17 + 256 + 256 + 64 + 64 + 512 + 512 + 128 + 128)
#define SMEM_BYTES  (SMEM_FLOATS * 4)

__device__ __forceinline__ void loadWchunk(const float* __restrict__ W, int k0, int t,
                                           float4& w0, float4& w1) {
    // chunk = rows [k0, k0+16) x 128 cols; 512 float4s over 256 threads (2 each)
    const float4* W4 = (const float4*)W;
    int kk0 = t >> 5;          // 0..7
    int c4  = t & 31;          // 0..31
    w0 = W4[(size_t)(k0 + kk0)     * 32 + c4];
    w1 = W4[(size_t)(k0 + 8 + kk0) * 32 + c4];
}

__device__ __forceinline__ void storeWchunk(float* sW, int t, const float4& w0, const float4& w1) {
    int kk0 = t >> 5;
    int c4  = t & 31;
    *(float4*)&sW[kk0 * 128 + c4 * 4]       = w0;
    *(float4*)&sW[(kk0 + 8) * 128 + c4 * 4] = w1;
}

__device__ __forceinline__ void fma16(const float* __restrict__ Ain, int astride, int kb,
                                      const float* __restrict__ sW, int r0, int c0,
                                      float acc[4][8]) {
#pragma unroll
    for (int kk = 0; kk < 16; ++kk) {
        float a[4];
#pragma unroll
        for (int i = 0; i < 4; ++i) a[i] = Ain[(r0 + i) * astride + kb + kk];
        float4 wv0 = *(const float4*)&sW[kk * 128 + c0];
        float4 wv1 = *(const float4*)&sW[kk * 128 + c0 + 4];
        float w[8] = {wv0.x, wv0.y, wv0.z, wv0.w, wv1.x, wv1.y, wv1.z, wv1.w};
#pragma unroll
        for (int i = 0; i < 4; ++i)
#pragma unroll
            for (int j = 0; j < 8; ++j) acc[i][j] = fmaf(a[i], w[j], acc[i][j]);
    }
}

// 64x128 <- 64x128 @ 128x128, A in smem (stride HP), weights streamed via sW chunks
__device__ __forceinline__ void gemm128_smemA(const float* __restrict__ Ain,
                                              const float* __restrict__ Wg,
                                              const float* __restrict__ bg,
                                              float* __restrict__ Hout,
                                              float* sW, int t, int r0, int c0, bool relu) {
    float acc[4][8];
#pragma unroll
    for (int i = 0; i < 4; ++i)
#pragma unroll
        for (int j = 0; j < 8; ++j) acc[i][j] = 0.f;

    float4 w0, w1;
    loadWchunk(Wg, 0, t, w0, w1);
    for (int ch = 0; ch < 8; ++ch) {
        storeWchunk(sW, t, w0, w1);
        __syncthreads();
        if (ch + 1 < 8) loadWchunk(Wg, (ch + 1) * 16, t, w0, w1);
        fma16(Ain, HP, ch * 16, sW, r0, c0, acc);
        __syncthreads();
    }
    float4 ba = *(const float4*)(bg + c0);
    float4 bb4 = *(const float4*)(bg + c0 + 4);
    float bb[8] = {ba.x, ba.y, ba.z, ba.w, bb4.x, bb4.y, bb4.z, bb4.w};
#pragma unroll
    for (int i = 0; i < 4; ++i)
#pragma unroll
        for (int j = 0; j < 8; ++j) {
            float v = acc[i][j] + bb[j];
            Hout[(r0 + i) * HP + c0 + j] = relu ? fmaxf(v, 0.f) : v;
        }
    __syncthreads();
}

// 4x128 <- 4x128 @ 128x128, A in smem (stride 128), W straight from global (L2 resident)
__device__ __forceinline__ void nodeGemm(const float* __restrict__ Ain,
                                         const float* __restrict__ Wg,
                                         const float* __restrict__ bg,
                                         float* __restrict__ Hout, int t, bool relu) {
    int o  = t & 127;
    int qb = (t >> 7) * 2;     // handles rows qb, qb+1
    float a0 = 0.f, a1 = 0.f;
#pragma unroll 8
    for (int k = 0; k < 128; ++k) {
        float w = __ldg(Wg + k * Dm + o);
        a0 = fmaf(Ain[qb * 128 + k], w, a0);
        a1 = fmaf(Ain[(qb + 1) * 128 + k], w, a1);
    }
    float b = __ldg(bg + o);
    float v0 = a0 + b, v1 = a1 + b;
    if (relu) { v0 = fmaxf(v0, 0.f); v1 = fmaxf(v1, 0.f); }
    Hout[qb * 128 + o]       = v0;
    Hout[(qb + 1) * 128 + o] = v1;
    __syncthreads();
}

__global__ void __launch_bounds__(NTHREADS, 2)
mpnn_fused(const float* __restrict__ x,
           const float* __restrict__ edge_attr,
           const int* __restrict__ receivers,
           const int* __restrict__ senders,
           const float* __restrict__ eW0, const float* __restrict__ eb0,
           const float* __restrict__ eW1, const float* __restrict__ eb1,
           const float* __restrict__ eW2, const float* __restrict__ eb2,
           const float* __restrict__ eg,  const float* __restrict__ ebeta,
           const float* __restrict__ nW0, const float* __restrict__ nb0,
           const float* __restrict__ nW1, const float* __restrict__ nb1,
           const float* __restrict__ nW2, const float* __restrict__ nb2,
           const float* __restrict__ ng,  const float* __restrict__ nbeta,
           float* __restrict__ out) {
    extern __shared__ float sm[];
    float* sHa    = sm;
    float* sHb    = sHa + EPB * HP;
    float* sW     = sHb + EPB * HP;
    float* sA     = sW + 16 * 128;
    float* sRed   = sA + EPB * 17;
    float* sRedSq = sRed + 256;
    float* sMu    = sRedSq + 256;
    float* sRs    = sMu + 64;
    float* sNin   = sRs + 64;
    float* sNx    = sNin + NPB * 128;
    float* sEg    = sNx + NPB * 128;
    float* sEb    = sEg + 128;

    const int t        = threadIdx.x;
    const int nodeBase = blockIdx.x * NPB;
    const int edgeBase = blockIdx.x * EPB;

    if (t < 128) { sEg[t] = eg[t]; sEb[t] = ebeta[t]; }

    const int trow = t >> 4, tcol = t & 15;
    const int r0 = trow * 4, c0 = tcol * 8;

    // ---------------- edge layer 0: [64,384] @ [384,128] ----------------
    const int  arow = t >> 2, aseg = t & 3;
    const long eIdx = (long)edgeBase + arow;
    const long rOff = (long)receivers[eIdx] * Dm;
    const long sOff = (long)senders[eIdx] * Dm;
    const float* attrRow = edge_attr + eIdx * Dm;

    float acc[4][8];
#pragma unroll
    for (int i = 0; i < 4; ++i)
#pragma unroll
        for (int j = 0; j < 8; ++j) acc[i][j] = 0.f;

    float4 aReg = *(const float4*)(x + rOff + aseg * 4);   // chunk 0 is in x[recv]
    float4 w0, w1;
    loadWchunk(eW0, 0, t, w0, w1);

    for (int ch = 0; ch < 24; ++ch) {
        sA[arow * 17 + aseg * 4 + 0] = aReg.x;
        sA[arow * 17 + aseg * 4 + 1] = aReg.y;
        sA[arow * 17 + aseg * 4 + 2] = aReg.z;
        sA[arow * 17 + aseg * 4 + 3] = aReg.w;
        storeWchunk(sW, t, w0, w1);
        __syncthreads();
        if (ch + 1 < 24) {                      // prefetch next chunk
            int k0  = (ch + 1) * 16;
            int col = k0 + aseg * 4;
            const float* p;
            if (k0 < 128)       p = x + rOff + col;
            else if (k0 < 256)  p = x + sOff + (col - 128);
            else                p = attrRow + (col - 256);
            aReg = *(const float4*)p;
            loadWchunk(eW0, k0, t, w0, w1);
        }
        fma16(sA, 17, 0, sW, r0, c0, acc);
        __syncthreads();
    }
    {   // bias + relu -> sHa
        float4 ba = *(const float4*)(eb0 + c0);
        float4 bb4 = *(const float4*)(eb0 + c0 + 4);
        float bb[8] = {ba.x, ba.y, ba.z, ba.w, bb4.x, bb4.y, bb4.z, bb4.w};
#pragma unroll
        for (int i = 0; i < 4; ++i)
#pragma unroll
            for (int j = 0; j < 8; ++j)
                sHa[(r0 + i) * HP + c0 + j] = fmaxf(acc[i][j] + bb[j], 0.f);
    }
    __syncthreads();

    // ---------------- edge layers 1, 2 ----------------
    gemm128_smemA(sHa, eW1, eb1, sHb, sW, t, r0, c0, true);
    gemm128_smemA(sHb, eW2, eb2, sHa, sW, t, r0, c0, false);   // raw pre-LN in sHa

    // ---------------- edge LayerNorm stats ----------------
    {
        int rrow = t & 63, part = t >> 6;
        float s = 0.f, sq = 0.f;
#pragma unroll
        for (int c = 0; c < 32; ++c) {
            float v = sHa[rrow * HP + part * 32 + c];
            s += v; sq += v * v;
        }
        sRed[rrow * 4 + part]   = s;
        sRedSq[rrow * 4 + part] = sq;
    }
    __syncthreads();
    if (t < 64) {
        float s  = sRed[t * 4] + sRed[t * 4 + 1] + sRed[t * 4 + 2] + sRed[t * 4 + 3];
        float sq = sRedSq[t * 4] + sRedSq[t * 4 + 1] + sRedSq[t * 4 + 2] + sRedSq[t * 4 + 3];
        float mu  = s * (1.f / 128.f);
        float var = sq * (1.f / 128.f) - mu * mu;
        sMu[t] = mu;
        sRs[t] = rsqrtf(var + 1e-5f);
    }
    __syncthreads();

    // ---------------- LN-apply fused with view(N,128,16).sum(-1) ----------------
    // node_in[q][i] = sum_{j<16} LN(m)[q*16 + i/8][(i%8)*16 + j]
#pragma unroll
    for (int u = t; u < NPB * 128; u += NTHREADS) {
        int q = u >> 7, i = u & 127;
        int lrow = q * 16 + (i >> 3);
        int d0   = (i & 7) * 16;
        float mu = sMu[lrow], rs = sRs[lrow];
        float av = 0.f;
#pragma unroll
        for (int j = 0; j < 16; ++j) {
            float v = (sHa[lrow * HP + d0 + j] - mu) * rs;
            av += v * sEg[d0 + j] + sEb[d0 + j];
        }
        sNin[q * 128 + i] = av;
    }
    __syncthreads();

    // ---------------- node MLP ----------------
    nodeGemm(sNin, nW0, nb0, sNx,  t, true);
    nodeGemm(sNx,  nW1, nb1, sNin, t, true);
    nodeGemm(sNin, nW2, nb2, sNx,  t, false);   // raw pre-LN in sNx

    // ---------------- node LayerNorm + write ----------------
    {
        int wq = t >> 5, lane = t & 31;
        if (wq < 4) {
            float s = 0.f, sq = 0.f;
#pragma unroll
            for (int c = lane; c < 128; c += 32) {
                float v = sNx[wq * 128 + c];
                s += v; sq += v * v;
            }
#pragma unroll
            for (int off = 16; off > 0; off >>= 1) {
                s  += __shfl_xor_sync(0xffffffffu, s,  off);
                sq += __shfl_xor_sync(0xffffffffu, sq, off);
            }
            if (lane == 0) {
                float mu  = s * (1.f / 128.f);
                float var = sq * (1.f / 128.f) - mu * mu;
                sMu[wq] = mu;
                sRs[wq] = rsqrtf(var + 1e-5f);
            }
        }
    }
    __syncthreads();
#pragma unroll
    for (int u = t; u < NPB * 128; u += NTHREADS) {
        int q = u >> 7, o = u & 127;
        out[(long)(nodeBase + q) * Dm + o] =
            (sNx[q * 128 + o] - sMu[q]) * sRs[q] * __ldg(ng + o) + __ldg(nbeta + o);
    }
}

extern "C" void kernel_launch(void* const* d_in, const int* in_sizes, int n_in,
                              void* d_out, int out_size) {
    const float* x         = (const float*)d_in[0];
    const float* edge_attr = (const float*)d_in[1];
    const int*   receivers = (const int*)d_in[2];
    const int*   senders   = (const int*)d_in[3];

    // Locate eW0 (3*D*D = 49152 elems) to be robust to whether the scalar
    // n_atoms input is materialized at index 4 or omitted.
    int wi = 4;
    while (wi < n_in && in_sizes[wi] != 3 * Dm * Dm) wi++;
    if (wi >= n_in) wi = (in_sizes[4] == 1) ? 5 : 4;

    const float* eW0   = (const float*)d_in[wi + 0];
    const float* eb0   = (const float*)d_in[wi + 1];
    const float* eW1   = (const float*)d_in[wi + 2];
    const float* eb1   = (const float*)d_in[wi + 3];
    const float* eW2   = (const float*)d_in[wi + 4];
    const float* eb2   = (const float*)d_in[wi + 5];
    const float* eg    = (const float*)d_in[wi + 6];
    const float* ebeta = (const float*)d_in[wi + 7];
    const float* nW0   = (const float*)d_in[wi + 8];
    const float* nb0   = (const float*)d_in[wi + 9];
    const float* nW1   = (const float*)d_in[wi + 10];
    const float* nb1   = (const float*)d_in[wi + 11];
    const float* nW2   = (const float*)d_in[wi + 12];
    const float* nb2   = (const float*)d_in[wi + 13];
    const float* ng    = (const float*)d_in[wi + 14];
    const float* nbeta = (const float*)d_in[wi + 15];

    int n_atoms = out_size / Dm;                  // 20000
    int blocks  = n_atoms / NPB;                  // 5000

    cudaFuncSetAttribute(mpnn_fused, cudaFuncAttributeMaxDynamicSharedMemorySize, SMEM_BYTES);
    mpnn_fused<<<blocks, NTHREADS, SMEM_BYTES>>>(
        x, edge_attr, receivers, senders,
        eW0, eb0, eW1, eb1, eW2, eb2, eg, ebeta,
        nW0, nb0, nW1, nb1, nW2, nb2, ng, nbeta,
        (float*)d_out);
}

// round 3
// speedup vs baseline: 3.1594x; 3.1594x over previous
#include <cuda_runtime.h>
#include <cuda_bf16.h>
#include <cstdint>

// ============================================================================
// MPNN on sm_103 (base target — no tcgen05!) via portable warp-level
// mma.sync m16n8k16 bf16 with split-bf16 3-pass for fp32-class accuracy.
//   prep:  weights -> hi/lo bf16 packed in exact mma B-fragment layout (global)
//   edge:  CTA=128 edges: gather -> 3-layer MLP (HMMA) -> LN -> local K=16
//          aggregation -> g_nodein
//   node:  CTA=128 nodes: 3-layer MLP (HMMA) -> LN -> out
// ============================================================================

#define STRB 272                 // A-smem row stride in bytes (136 bf16)
#define AH_OFF 0
#define AL_OFF 34816
#define PS_OFF 69632
#define PQ_OFF 70656
#define MU_OFF 71680
#define RS_OFF 72192
#define SMEM_TOTAL 72704

// B fragments: 1024 tiles (k16 x n8) * 32 lanes * 2 regs * 2 bf16
__device__ __align__(16) unsigned short g_Bh[1024 * 32 * 4];
__device__ __align__(16) unsigned short g_Bl[1024 * 32 * 4];
__device__ float g_nodein[20000 * 128];

// tile bases (units: one k16xn8 fragment tile = 32 lanes * 8B)
#define TB_EW0 0      // K=384 -> 24*16 = 384 tiles
#define TB_EW1 384
#define TB_EW2 512
#define TB_NW0 640
#define TB_NW1 768
#define TB_NW2 896

// ============================ helpers =======================================
__device__ __forceinline__ uint32_t smem_u32(const void* p) {
    uint32_t a;
    asm("{ .reg .u64 t; cvta.to.shared.u64 t, %1; cvt.u32.u64 %0, t; }" : "=r"(a) : "l"(p));
    return a;
}

__device__ __forceinline__ void ldmA(uint32_t addr, uint32_t a[4]) {
    asm volatile("ldmatrix.sync.aligned.m8n8.x4.shared.b16 {%0,%1,%2,%3}, [%4];"
                 : "=r"(a[0]), "=r"(a[1]), "=r"(a[2]), "=r"(a[3]) : "r"(addr));
}

__device__ __forceinline__ void mmabf(float* c, const uint32_t a[4], uint2 b) {
    asm volatile(
        "mma.sync.aligned.m16n8k16.row.col.f32.bf16.bf16.f32 "
        "{%0,%1,%2,%3}, {%4,%5,%6,%7}, {%8,%9}, {%0,%1,%2,%3};"
        : "+f"(c[0]), "+f"(c[1]), "+f"(c[2]), "+f"(c[3])
        : "r"(a[0]), "r"(a[1]), "r"(a[2]), "r"(a[3]), "r"(b.x), "r"(b.y));
}

__device__ __forceinline__ void split2(float a, float b, uint32_t& hp, uint32_t& lp) {
    __nv_bfloat162 H = __floats2bfloat162_rn(a, b);
    float ra = a - __bfloat162float(H.x);
    float rb = b - __bfloat162float(H.y);
    __nv_bfloat162 L = __floats2bfloat162_rn(ra, rb);
    hp = *reinterpret_cast<uint32_t*>(&H);
    lp = *reinterpret_cast<uint32_t*>(&L);
}

__device__ __forceinline__ void split4(float4 v, uint2& hp, uint2& lp) {
    split2(v.x, v.y, hp.x, lp.x);
    split2(v.z, v.w, hp.y, lp.y);
}

// stage 64 cols of one row into Ah/Al smem (split bf16)
__device__ __forceinline__ void stageA(char* sm, const float* __restrict__ src,
                                       int lr, int colbase) {
#pragma unroll
    for (int q = 0; q < 16; ++q) {
        float4 v = *reinterpret_cast<const float4*>(src + q * 4);
        uint2 hp, lp;
        split4(v, hp, lp);
        int off = lr * STRB + (colbase + q * 4) * 2;
        *reinterpret_cast<uint2*>(sm + AH_OFF + off) = hp;
        *reinterpret_cast<uint2*>(sm + AL_OFF + off) = lp;
    }
}

// one 128-col K-chunk of a layer: 8 k-steps, 3 mma passes (AhBh, AhBl, AlBh)
__device__ __forceinline__ void mma_layer(float C[2][8][4], uint32_t smb,
                                          int LB, int soff, int lane, int wm, int wn) {
    const uint2* BH = reinterpret_cast<const uint2*>(g_Bh);
    const uint2* BL = reinterpret_cast<const uint2*>(g_Bl);
    const int rowoff = ((lane >> 3) & 1) * 8 + (lane & 7);
    const int choff  = lane >> 4;
#pragma unroll
    for (int s = 0; s < 8; ++s) {
        int tb = (LB + (soff + s) * 16 + wn * 8) * 32 + lane;
        uint2 bh[8], bl[8];
#pragma unroll
        for (int nt = 0; nt < 8; ++nt) {
            bh[nt] = __ldg(&BH[tb + nt * 32]);
            bl[nt] = __ldg(&BL[tb + nt * 32]);
        }
        uint32_t ah[2][4], al[2][4];
#pragma unroll
        for (int mi = 0; mi < 2; ++mi) {
            uint32_t base = smb + (uint32_t)((wm * 32 + mi * 16 + rowoff) * STRB
                                             + (s * 2 + choff) * 16);
            ldmA(base + AH_OFF, ah[mi]);
            ldmA(base + AL_OFF, al[mi]);
        }
#pragma unroll
        for (int mi = 0; mi < 2; ++mi)
#pragma unroll
            for (int nt = 0; nt < 8; ++nt) {
                mmabf(C[mi][nt], ah[mi], bh[nt]);
                mmabf(C[mi][nt], ah[mi], bl[nt]);
                mmabf(C[mi][nt], al[mi], bh[nt]);
            }
    }
}

// bias + ReLU + split -> rewrite A smem for next layer; zero C
__device__ __forceinline__ void epi_relu(float C[2][8][4], char* sm,
                                         const float* __restrict__ bias,
                                         int lane, int wm, int wn) {
    const int grp = lane >> 2, tig = lane & 3;
#pragma unroll
    for (int mi = 0; mi < 2; ++mi)
#pragma unroll
        for (int nt = 0; nt < 8; ++nt) {
            int col0 = wn * 64 + nt * 8 + tig * 2;
            int row  = wm * 32 + mi * 16 + grp;
            float b0 = __ldg(bias + col0), b1 = __ldg(bias + col0 + 1);
            float v0 = fmaxf(C[mi][nt][0] + b0, 0.f);
            float v1 = fmaxf(C[mi][nt][1] + b1, 0.f);
            float v2 = fmaxf(C[mi][nt][2] + b0, 0.f);
            float v3 = fmaxf(C[mi][nt][3] + b1, 0.f);
            uint32_t h, l;
            split2(v0, v1, h, l);
            *reinterpret_cast<uint32_t*>(sm + AH_OFF + row * STRB + col0 * 2) = h;
            *reinterpret_cast<uint32_t*>(sm + AL_OFF + row * STRB + col0 * 2) = l;
            split2(v2, v3, h, l);
            *reinterpret_cast<uint32_t*>(sm + AH_OFF + (row + 8) * STRB + col0 * 2) = h;
            *reinterpret_cast<uint32_t*>(sm + AL_OFF + (row + 8) * STRB + col0 * 2) = l;
            C[mi][nt][0] = C[mi][nt][1] = C[mi][nt][2] = C[mi][nt][3] = 0.f;
        }
}

// add bias in place, compute per-row LN stats (mu, rs) for this lane's 4 rows
__device__ __forceinline__ void ln_stats(float C[2][8][4], char* sm,
                                         const float* __restrict__ bias,
                                         int t, int lane, int wm, int wn,
                                         float mu[2][2], float rs[2][2]) {
    const int grp = lane >> 2, tig = lane & 3;
    float s[2][2] = {{0.f, 0.f}, {0.f, 0.f}};
    float q[2][2] = {{0.f, 0.f}, {0.f, 0.f}};
#pragma unroll
    for (int mi = 0; mi < 2; ++mi)
#pragma unroll
        for (int nt = 0; nt < 8; ++nt) {
            int col0 = wn * 64 + nt * 8 + tig * 2;
            float b0 = __ldg(bias + col0), b1 = __ldg(bias + col0 + 1);
            C[mi][nt][0] += b0; C[mi][nt][1] += b1;
            C[mi][nt][2] += b0; C[mi][nt][3] += b1;
            s[mi][0] += C[mi][nt][0] + C[mi][nt][1];
            q[mi][0] += C[mi][nt][0] * C[mi][nt][0] + C[mi][nt][1] * C[mi][nt][1];
            s[mi][1] += C[mi][nt][2] + C[mi][nt][3];
            q[mi][1] += C[mi][nt][2] * C[mi][nt][2] + C[mi][nt][3] * C[mi][nt][3];
        }
#pragma unroll
    for (int off = 1; off <= 2; off <<= 1)
#pragma unroll
        for (int mi = 0; mi < 2; ++mi)
#pragma unroll
            for (int h = 0; h < 2; ++h) {
                s[mi][h] += __shfl_xor_sync(0xffffffffu, s[mi][h], off);
                q[mi][h] += __shfl_xor_sync(0xffffffffu, q[mi][h], off);
            }
    float* ps = reinterpret_cast<float*>(sm + PS_OFF);
    float* pq = reinterpret_cast<float*>(sm + PQ_OFF);
    if (tig == 0) {
#pragma unroll
        for (int mi = 0; mi < 2; ++mi)
#pragma unroll
            for (int h = 0; h < 2; ++h) {
                int row = wm * 32 + mi * 16 + grp + h * 8;
                ps[wn * 128 + row] = s[mi][h];
                pq[wn * 128 + row] = q[mi][h];
            }
    }
    __syncthreads();
    float* smu = reinterpret_cast<float*>(sm + MU_OFF);
    float* srs = reinterpret_cast<float*>(sm + RS_OFF);
    if (t < 128) {
        float su = ps[t] + ps[128 + t];
        float sq = pq[t] + pq[128 + t];
        float m  = su * (1.f / 128.f);
        float v  = sq * (1.f / 128.f) - m * m;
        smu[t] = m;
        srs[t] = rsqrtf(v + 1e-5f);
    }
    __syncthreads();
#pragma unroll
    for (int mi = 0; mi < 2; ++mi)
#pragma unroll
        for (int h = 0; h < 2; ++h) {
            int row = wm * 32 + mi * 16 + grp + h * 8;
            mu[mi][h] = smu[row];
            rs[mi][h] = srs[row];
        }
}

// ============================ kernels =======================================
__global__ void prep_w(const float* __restrict__ W, int K, int tileBase) {
    int idx = blockIdx.x * 256 + threadIdx.x;
    if (idx >= K * 128) return;
    int k = idx >> 7, n = idx & 127;
    float wv = W[idx];
    __nv_bfloat16 h = __float2bfloat16(wv);
    __nv_bfloat16 l = __float2bfloat16(wv - __bfloat162float(h));
    int klocal = k & 15;
    int tile = tileBase + (k >> 4) * 16 + (n >> 3);
    int lane = (n & 7) * 4 + ((klocal >> 1) & 3);
    int reg  = (klocal >> 3) & 1;
    int half = klocal & 1;
    int pos = ((tile * 32 + lane) * 2 + reg) * 2 + half;
    g_Bh[pos] = *reinterpret_cast<unsigned short*>(&h);
    g_Bl[pos] = *reinterpret_cast<unsigned short*>(&l);
}

__global__ void __launch_bounds__(256, 1)
mpnn_edge(const float* __restrict__ x, const float* __restrict__ eattr,
          const int* __restrict__ recv, const int* __restrict__ send,
          const float* __restrict__ eb0, const float* __restrict__ eb1,
          const float* __restrict__ eb2, const float* __restrict__ eg,
          const float* __restrict__ ebeta) {
    extern __shared__ char sm[];
    const uint32_t smb = smem_u32(sm);
    const int t = threadIdx.x, lane = t & 31, w = t >> 5;
    const int wm = w & 3, wn = w >> 2;
    const long e0 = (long)blockIdx.x * 128;
    const int lr = t >> 1, half = t & 1;
    const long re = (long)__ldg(recv + e0 + lr) * 128;
    const long se = (long)__ldg(send + e0 + lr) * 128;

    float C[2][8][4];
#pragma unroll
    for (int mi = 0; mi < 2; ++mi)
#pragma unroll
        for (int nt = 0; nt < 8; ++nt)
#pragma unroll
            for (int e = 0; e < 4; ++e) C[mi][nt][e] = 0.f;

    // ------- layer 0: K=384, three 128-col chunks -------
#pragma unroll 1
    for (int c = 0; c < 3; ++c) {
        const float* src = (c == 0) ? x + re
                         : (c == 1) ? x + se
                                    : eattr + (e0 + lr) * 128;
        stageA(sm, src + half * 64, lr, half * 64);
        __syncthreads();
        mma_layer(C, smb, TB_EW0, c * 8, lane, wm, wn);
        __syncthreads();
    }
    epi_relu(C, sm, eb0, lane, wm, wn);
    __syncthreads();
    mma_layer(C, smb, TB_EW1, 0, lane, wm, wn);
    __syncthreads();
    epi_relu(C, sm, eb1, lane, wm, wn);
    __syncthreads();
    mma_layer(C, smb, TB_EW2, 0, lane, wm, wn);

    float mu[2][2], rs[2][2];
    ln_stats(C, sm, eb2, t, lane, wm, wn, mu, rs);

    // LN-apply (with eg/ebeta) into fp32 smem buffer (reuses A region)
    float* sF = reinterpret_cast<float*>(sm);
    const int grp = lane >> 2, tig = lane & 3;
#pragma unroll
    for (int mi = 0; mi < 2; ++mi)
#pragma unroll
        for (int nt = 0; nt < 8; ++nt) {
            int col0 = wn * 64 + nt * 8 + tig * 2;
            int r1   = wm * 32 + mi * 16 + grp;
            float g0 = __ldg(eg + col0),    g1 = __ldg(eg + col0 + 1);
            float be0 = __ldg(ebeta + col0), be1 = __ldg(ebeta + col0 + 1);
            float2 o1 = {(C[mi][nt][0] - mu[mi][0]) * rs[mi][0] * g0 + be0,
                         (C[mi][nt][1] - mu[mi][0]) * rs[mi][0] * g1 + be1};
            float2 o2 = {(C[mi][nt][2] - mu[mi][1]) * rs[mi][1] * g0 + be0,
                         (C[mi][nt][3] - mu[mi][1]) * rs[mi][1] * g1 + be1};
            *reinterpret_cast<float2*>(sF + r1 * 132 + col0)       = o1;
            *reinterpret_cast<float2*>(sF + (r1 + 8) * 132 + col0) = o2;
        }
    __syncthreads();

    // block-local aggregation: node_in[q][d] = sum_j m[q*16 + d/8][(d%8)*16 + j]
#pragma unroll
    for (int u = t; u < 1024; u += 256) {
        int qn = u >> 7, d = u & 127;
        int rrow = qn * 16 + (d >> 3), cb = (d & 7) * 16;
        const float* p = sF + rrow * 132 + cb;
        float acc = 0.f;
#pragma unroll
        for (int j = 0; j < 16; ++j) acc += p[j];
        g_nodein[((e0 >> 4) + qn) * 128 + d] = acc;
    }
}

__global__ void __launch_bounds__(256, 1)
mpnn_node(const float* __restrict__ nb0, const float* __restrict__ nb1,
          const float* __restrict__ nb2, const float* __restrict__ ng,
          const float* __restrict__ nbeta, float* __restrict__ out, int natoms) {
    extern __shared__ char sm[];
    const uint32_t smb = smem_u32(sm);
    const int t = threadIdx.x, lane = t & 31, w = t >> 5;
    const int wm = w & 3, wn = w >> 2;
    const long r0 = (long)blockIdx.x * 128;
    const int lr = t >> 1, half = t & 1;

    {   // stage A from g_nodein (zero-pad tail rows)
        bool valid = (r0 + lr) < natoms;
        const float* src = g_nodein + (r0 + lr) * 128 + half * 64;
#pragma unroll
        for (int q2 = 0; q2 < 16; ++q2) {
            float4 v = valid ? *reinterpret_cast<const float4*>(src + q2 * 4)
                             : make_float4(0.f, 0.f, 0.f, 0.f);
            uint2 hp, lp;
            split4(v, hp, lp);
            int off = lr * STRB + (half * 64 + q2 * 4) * 2;
            *reinterpret_cast<uint2*>(sm + AH_OFF + off) = hp;
            *reinterpret_cast<uint2*>(sm + AL_OFF + off) = lp;
        }
    }
    __syncthreads();

    float C[2][8][4];
#pragma unroll
    for (int mi = 0; mi < 2; ++mi)
#pragma unroll
        for (int nt = 0; nt < 8; ++nt)
#pragma unroll
            for (int e = 0; e < 4; ++e) C[mi][nt][e] = 0.f;

    mma_layer(C, smb, TB_NW0, 0, lane, wm, wn);
    __syncthreads();
    epi_relu(C, sm, nb0, lane, wm, wn);
    __syncthreads();
    mma_layer(C, smb, TB_NW1, 0, lane, wm, wn);
    __syncthreads();
    epi_relu(C, sm, nb1, lane, wm, wn);
    __syncthreads();
    mma_layer(C, smb, TB_NW2, 0, lane, wm, wn);

    float mu[2][2], rs[2][2];
    ln_stats(C, sm, nb2, t, lane, wm, wn, mu, rs);

    const int grp = lane >> 2, tig = lane & 3;
#pragma unroll
    for (int mi = 0; mi < 2; ++mi)
#pragma unroll
        for (int nt = 0; nt < 8; ++nt) {
            int col0 = wn * 64 + nt * 8 + tig * 2;
            int r1   = wm * 32 + mi * 16 + grp;
            float g0 = __ldg(ng + col0),     g1 = __ldg(ng + col0 + 1);
            float be0 = __ldg(nbeta + col0), be1 = __ldg(nbeta + col0 + 1);
            if (r0 + r1 < natoms) {
                float2 o1 = {(C[mi][nt][0] - mu[mi][0]) * rs[mi][0] * g0 + be0,
                             (C[mi][nt][1] - mu[mi][0]) * rs[mi][0] * g1 + be1};
                *reinterpret_cast<float2*>(out + (r0 + r1) * 128 + col0) = o1;
            }
            if (r0 + r1 + 8 < natoms) {
                float2 o2 = {(C[mi][nt][2] - mu[mi][1]) * rs[mi][1] * g0 + be0,
                             (C[mi][nt][3] - mu[mi][1]) * rs[mi][1] * g1 + be1};
                *reinterpret_cast<float2*>(out + (r0 + r1 + 8) * 128 + col0) = o2;
            }
        }
}

// ============================ launch ========================================
extern "C" void kernel_launch(void* const* d_in, const int* in_sizes, int n_in,
                              void* d_out, int out_size) {
    const float* x         = (const float*)d_in[0];
    const float* edge_attr = (const float*)d_in[1];
    const int*   receivers = (const int*)d_in[2];
    const int*   senders   = (const int*)d_in[3];

    int wi = 4;
    while (wi < n_in && in_sizes[wi] != 3 * 128 * 128) wi++;
    if (wi >= n_in) wi = (in_sizes[4] == 1) ? 5 : 4;

    const float* eW0   = (const float*)d_in[wi + 0];
    const float* eb0   = (const float*)d_in[wi + 1];
    const float* eW1   = (const float*)d_in[wi + 2];
    const float* eb1   = (const float*)d_in[wi + 3];
    const float* eW2   = (const float*)d_in[wi + 4];
    const float* eb2   = (const float*)d_in[wi + 5];
    const float* eg    = (const float*)d_in[wi + 6];
    const float* ebeta = (const float*)d_in[wi + 7];
    const float* nW0   = (const float*)d_in[wi + 8];
    const float* nb0   = (const float*)d_in[wi + 9];
    const float* nW1   = (const float*)d_in[wi + 10];
    const float* nb1   = (const float*)d_in[wi + 11];
    const float* nW2   = (const float*)d_in[wi + 12];
    const float* nb2   = (const float*)d_in[wi + 13];
    const float* ng    = (const float*)d_in[wi + 14];
    const float* nbeta = (const float*)d_in[wi + 15];

    int E      = in_sizes[2];
    int natoms = out_size / 128;

    cudaFuncSetAttribute(mpnn_edge, cudaFuncAttributeMaxDynamicSharedMemorySize, SMEM_TOTAL);
    cudaFuncSetAttribute(mpnn_node, cudaFuncAttributeMaxDynamicSharedMemorySize, SMEM_TOTAL);

    prep_w<<<192, 256>>>(eW0, 384, TB_EW0);
    prep_w<<<64,  256>>>(eW1, 128, TB_EW1);
    prep_w<<<64,  256>>>(eW2, 128, TB_EW2);
    prep_w<<<64,  256>>>(nW0, 128, TB_NW0);
    prep_w<<<64,  256>>>(nW1, 128, TB_NW1);
    prep_w<<<64,  256>>>(nW2, 128, TB_NW2);

    mpnn_edge<<<E / 128, 256, SMEM_TOTAL>>>(x, edge_attr, receivers, senders,
                                            eb0, eb1, eb2, eg, ebeta);
    mpnn_node<<<(natoms + 127) / 128, 256, SMEM_TOTAL>>>(nb0, nb1, nb2, ng, nbeta,
                                                         (float*)d_out, natoms);
}

// round 4
// speedup vs baseline: 3.5594x; 1.1266x over previous
#include <cuda_runtime.h>
#include <cuda_bf16.h>
#include <cstdint>

// ============================================================================
// MPNN on sm_103 (base target — no tcgen05) via warp-level mma.sync m16n8k16
// bf16, split-bf16 3-pass (AhBh + AhBl + AlBh) for fp32-class accuracy.
//   prep (5 launches): weights -> interleaved hi/lo bf16 mma B-fragments
//   edge: CTA=128 edges: gather -> 3-layer MLP -> LN -> local K=16 agg -> g_nodein
//   node: CTA=128 nodes: 3-layer MLP -> LN -> out
// ============================================================================

#define STRB 272                 // A-smem row stride in bytes (136 bf16)
#define AH_OFF 0
#define AL_OFF 34816
#define PS_OFF 69632
#define PQ_OFF 70656
#define MU_OFF 71680
#define RS_OFF 72192
#define SMEM_TOTAL 72704

// B fragments: 1024 tiles (k16 x n8) * 32 lanes * uint4 {bh0,bh1,bl0,bl1}
__device__ __align__(16) uint4 g_B[1024 * 32];
__device__ float g_nodein[20000 * 128];

#define TB_EW0 0
#define TB_EW1 384
#define TB_EW2 512
#define TB_NW0 640
#define TB_NW1 768
#define TB_NW2 896

// ============================ helpers =======================================
__device__ __forceinline__ uint32_t smem_u32(const void* p) {
    uint32_t a;
    asm("{ .reg .u64 t; cvta.to.shared.u64 t, %1; cvt.u32.u64 %0, t; }" : "=r"(a) : "l"(p));
    return a;
}

__device__ __forceinline__ void ldmA(uint32_t addr, uint32_t a[4]) {
    asm volatile("ldmatrix.sync.aligned.m8n8.x4.shared.b16 {%0,%1,%2,%3}, [%4];"
                 : "=r"(a[0]), "=r"(a[1]), "=r"(a[2]), "=r"(a[3]) : "r"(addr));
}

__device__ __forceinline__ void mmabf(float* c, const uint32_t a[4], uint32_t b0, uint32_t b1) {
    asm volatile(
        "mma.sync.aligned.m16n8k16.row.col.f32.bf16.bf16.f32 "
        "{%0,%1,%2,%3}, {%4,%5,%6,%7}, {%8,%9}, {%0,%1,%2,%3};"
        : "+f"(c[0]), "+f"(c[1]), "+f"(c[2]), "+f"(c[3])
        : "r"(a[0]), "r"(a[1]), "r"(a[2]), "r"(a[3]), "r"(b0), "r"(b1));
}

__device__ __forceinline__ void split2(float a, float b, uint32_t& hp, uint32_t& lp) {
    __nv_bfloat162 H = __floats2bfloat162_rn(a, b);
    float ra = a - __bfloat162float(H.x);
    float rb = b - __bfloat162float(H.y);
    __nv_bfloat162 L = __floats2bfloat162_rn(ra, rb);
    hp = *reinterpret_cast<uint32_t*>(&H);
    lp = *reinterpret_cast<uint32_t*>(&L);
}

__device__ __forceinline__ void split4(float4 v, uint2& hp, uint2& lp) {
    split2(v.x, v.y, hp.x, lp.x);
    split2(v.z, v.w, hp.y, lp.y);
}

// stage 64 cols of one row into Ah/Al smem (split bf16)
__device__ __forceinline__ void stageA(char* sm, const float* __restrict__ src,
                                       int lr, int colbase) {
#pragma unroll
    for (int q = 0; q < 16; ++q) {
        float4 v = *reinterpret_cast<const float4*>(src + q * 4);
        uint2 hp, lp;
        split4(v, hp, lp);
        int off = lr * STRB + (colbase + q * 4) * 2;
        *reinterpret_cast<uint2*>(sm + AH_OFF + off) = hp;
        *reinterpret_cast<uint2*>(sm + AL_OFF + off) = lp;
    }
}

// one 128-col K-chunk of a layer: 8 k-steps, 3 mma passes (AhBh, AhBl, AlBh)
__device__ __forceinline__ void mma_layer(float C[2][8][4], uint32_t smb,
                                          int LB, int soff, int lane, int wm, int wn) {
    const int rowoff = ((lane >> 3) & 1) * 8 + (lane & 7);
    const int choff  = lane >> 4;
#pragma unroll
    for (int s = 0; s < 8; ++s) {
        uint32_t ah[2][4], al[2][4];
#pragma unroll
        for (int mi = 0; mi < 2; ++mi) {
            uint32_t base = smb + (uint32_t)((wm * 32 + mi * 16 + rowoff) * STRB
                                             + (s * 2 + choff) * 16);
            ldmA(base + AH_OFF, ah[mi]);
            ldmA(base + AL_OFF, al[mi]);
        }
        int tb = (LB + (soff + s) * 16 + wn * 8) * 32 + lane;
#pragma unroll
        for (int h = 0; h < 2; ++h) {
            uint4 bv[4];
#pragma unroll
            for (int j = 0; j < 4; ++j) bv[j] = __ldg(&g_B[tb + (h * 4 + j) * 32]);
#pragma unroll
            for (int mi = 0; mi < 2; ++mi)
#pragma unroll
                for (int j = 0; j < 4; ++j) {
                    float* c = C[mi][h * 4 + j];
                    mmabf(c, ah[mi], bv[j].x, bv[j].y);
                    mmabf(c, ah[mi], bv[j].z, bv[j].w);
                    mmabf(c, al[mi], bv[j].x, bv[j].y);
                }
        }
    }
}

// bias + ReLU + split -> rewrite A smem for next layer; zero C
__device__ __forceinline__ void epi_relu(float C[2][8][4], char* sm,
                                         const float* __restrict__ bias,
                                         int lane, int wm, int wn) {
    const int grp = lane >> 2, tig = lane & 3;
#pragma unroll
    for (int mi = 0; mi < 2; ++mi)
#pragma unroll
        for (int nt = 0; nt < 8; ++nt) {
            int col0 = wn * 64 + nt * 8 + tig * 2;
            int row  = wm * 32 + mi * 16 + grp;
            float b0 = __ldg(bias + col0), b1 = __ldg(bias + col0 + 1);
            float v0 = fmaxf(C[mi][nt][0] + b0, 0.f);
            float v1 = fmaxf(C[mi][nt][1] + b1, 0.f);
            float v2 = fmaxf(C[mi][nt][2] + b0, 0.f);
            float v3 = fmaxf(C[mi][nt][3] + b1, 0.f);
            uint32_t h, l;
            split2(v0, v1, h, l);
            *reinterpret_cast<uint32_t*>(sm + AH_OFF + row * STRB + col0 * 2) = h;
            *reinterpret_cast<uint32_t*>(sm + AL_OFF + row * STRB + col0 * 2) = l;
            split2(v2, v3, h, l);
            *reinterpret_cast<uint32_t*>(sm + AH_OFF + (row + 8) * STRB + col0 * 2) = h;
            *reinterpret_cast<uint32_t*>(sm + AL_OFF + (row + 8) * STRB + col0 * 2) = l;
            C[mi][nt][0] = C[mi][nt][1] = C[mi][nt][2] = C[mi][nt][3] = 0.f;
        }
}

// add bias in place, compute per-row LN stats (mu, rs) for this lane's 4 rows
__device__ __forceinline__ void ln_stats(float C[2][8][4], char* sm,
                                         const float* __restrict__ bias,
                                         int t, int lane, int wm, int wn,
                                         float mu[2][2], float rs[2][2]) {
    const int grp = lane >> 2, tig = lane & 3;
    float s[2][2] = {{0.f, 0.f}, {0.f, 0.f}};
    float q[2][2] = {{0.f, 0.f}, {0.f, 0.f}};
#pragma unroll
    for (int mi = 0; mi < 2; ++mi)
#pragma unroll
        for (int nt = 0; nt < 8; ++nt) {
            int col0 = wn * 64 + nt * 8 + tig * 2;
            float b0 = __ldg(bias + col0), b1 = __ldg(bias + col0 + 1);
            C[mi][nt][0] += b0; C[mi][nt][1] += b1;
            C[mi][nt][2] += b0; C[mi][nt][3] += b1;
            s[mi][0] += C[mi][nt][0] + C[mi][nt][1];
            q[mi][0] += C[mi][nt][0] * C[mi][nt][0] + C[mi][nt][1] * C[mi][nt][1];
            s[mi][1] += C[mi][nt][2] + C[mi][nt][3];
            q[mi][1] += C[mi][nt][2] * C[mi][nt][2] + C[mi][nt][3] * C[mi][nt][3];
        }
#pragma unroll
    for (int off = 1; off <= 2; off <<= 1)
#pragma unroll
        for (int mi = 0; mi < 2; ++mi)
#pragma unroll
            for (int h = 0; h < 2; ++h) {
                s[mi][h] += __shfl_xor_sync(0xffffffffu, s[mi][h], off);
                q[mi][h] += __shfl_xor_sync(0xffffffffu, q[mi][h], off);
            }
    float* ps = reinterpret_cast<float*>(sm + PS_OFF);
    float* pq = reinterpret_cast<float*>(sm + PQ_OFF);
    if (tig == 0) {
#pragma unroll
        for (int mi = 0; mi < 2; ++mi)
#pragma unroll
            for (int h = 0; h < 2; ++h) {
                int row = wm * 32 + mi * 16 + grp + h * 8;
                ps[wn * 128 + row] = s[mi][h];
                pq[wn * 128 + row] = q[mi][h];
            }
    }
    __syncthreads();
    float* smu = reinterpret_cast<float*>(sm + MU_OFF);
    float* srs = reinterpret_cast<float*>(sm + RS_OFF);
    if (t < 128) {
        float su = ps[t] + ps[128 + t];
        float sq = pq[t] + pq[128 + t];
        float m  = su * (1.f / 128.f);
        float v  = sq * (1.f / 128.f) - m * m;
        smu[t] = m;
        srs[t] = rsqrtf(v + 1e-5f);
    }
    __syncthreads();
#pragma unroll
    for (int mi = 0; mi < 2; ++mi)
#pragma unroll
        for (int h = 0; h < 2; ++h) {
            int row = wm * 32 + mi * 16 + grp + h * 8;
            mu[mi][h] = smu[row];
            rs[mi][h] = srs[row];
        }
}

// ============================ prep ==========================================
__device__ __forceinline__ void prep_one(const float* __restrict__ W, int idx, int tileBase) {
    int k = idx >> 7, n = idx & 127;
    float wv = W[idx];
    __nv_bfloat16 h = __float2bfloat16(wv);
    __nv_bfloat16 l = __float2bfloat16(wv - __bfloat162float(h));
    int klocal = k & 15;
    int tile = tileBase + (k >> 4) * 16 + (n >> 3);
    int lane = (n & 7) * 4 + ((klocal >> 1) & 3);
    int reg  = (klocal >> 3) & 1;
    int half = klocal & 1;
    unsigned short* gb = reinterpret_cast<unsigned short*>(g_B);
    int base = (tile * 32 + lane) * 8;
    gb[base + reg * 2 + half]     = *reinterpret_cast<unsigned short*>(&h);
    gb[base + 4 + reg * 2 + half] = *reinterpret_cast<unsigned short*>(&l);
}

__global__ void prep_w(const float* __restrict__ W, int K, int tileBase) {
    int idx = blockIdx.x * 256 + threadIdx.x;
    if (idx < K * 128) prep_one(W, idx, tileBase);
}

__global__ void prep_w2(const float* __restrict__ W1, int tb1,
                        const float* __restrict__ W2, int tb2) {
    int idx = blockIdx.x * 256 + threadIdx.x;
    if (idx < 128 * 128) {
        prep_one(W1, idx, tb1);
        prep_one(W2, idx, tb2);
    }
}

// ============================ kernels =======================================
__global__ void __launch_bounds__(256, 2)
mpnn_edge(const float* __restrict__ x, const float* __restrict__ eattr,
          const int* __restrict__ recv, const int* __restrict__ send,
          const float* __restrict__ eb0, const float* __restrict__ eb1,
          const float* __restrict__ eb2, const float* __restrict__ eg,
          const float* __restrict__ ebeta) {
    extern __shared__ char sm[];
    const uint32_t smb = smem_u32(sm);
    const int t = threadIdx.x, lane = t & 31, w = t >> 5;
    const int wm = w & 3, wn = w >> 2;
    const long e0 = (long)blockIdx.x * 128;
    const int lr = t >> 1, half = t & 1;
    const long re = (long)__ldg(recv + e0 + lr) * 128;
    const long se = (long)__ldg(send + e0 + lr) * 128;

    float C[2][8][4];
#pragma unroll
    for (int mi = 0; mi < 2; ++mi)
#pragma unroll
        for (int nt = 0; nt < 8; ++nt)
#pragma unroll
            for (int e = 0; e < 4; ++e) C[mi][nt][e] = 0.f;

    // ------- layer 0: K=384, three 128-col chunks -------
#pragma unroll 1
    for (int c = 0; c < 3; ++c) {
        const float* src = (c == 0) ? x + re
                         : (c == 1) ? x + se
                                    : eattr + (e0 + lr) * 128;
        stageA(sm, src + half * 64, lr, half * 64);
        __syncthreads();
        mma_layer(C, smb, TB_EW0, c * 8, lane, wm, wn);
        __syncthreads();
    }
    epi_relu(C, sm, eb0, lane, wm, wn);
    __syncthreads();
    mma_layer(C, smb, TB_EW1, 0, lane, wm, wn);
    __syncthreads();
    epi_relu(C, sm, eb1, lane, wm, wn);
    __syncthreads();
    mma_layer(C, smb, TB_EW2, 0, lane, wm, wn);

    float mu[2][2], rs[2][2];
    ln_stats(C, sm, eb2, t, lane, wm, wn, mu, rs);

    // LN-apply (with eg/ebeta) into fp32 smem buffer (reuses A region)
    float* sF = reinterpret_cast<float*>(sm);
    const int grp = lane >> 2, tig = lane & 3;
#pragma unroll
    for (int mi = 0; mi < 2; ++mi)
#pragma unroll
        for (int nt = 0; nt < 8; ++nt) {
            int col0 = wn * 64 + nt * 8 + tig * 2;
            int r1   = wm * 32 + mi * 16 + grp;
            float g0 = __ldg(eg + col0),    g1 = __ldg(eg + col0 + 1);
            float be0 = __ldg(ebeta + col0), be1 = __ldg(ebeta + col0 + 1);
            float2 o1 = {(C[mi][nt][0] - mu[mi][0]) * rs[mi][0] * g0 + be0,
                         (C[mi][nt][1] - mu[mi][0]) * rs[mi][0] * g1 + be1};
            float2 o2 = {(C[mi][nt][2] - mu[mi][1]) * rs[mi][1] * g0 + be0,
                         (C[mi][nt][3] - mu[mi][1]) * rs[mi][1] * g1 + be1};
            *reinterpret_cast<float2*>(sF + r1 * 132 + col0)       = o1;
            *reinterpret_cast<float2*>(sF + (r1 + 8) * 132 + col0) = o2;
        }
    __syncthreads();

    // block-local aggregation: node_in[q][d] = sum_j m[q*16 + d/8][(d%8)*16 + j]
#pragma unroll
    for (int u = t; u < 1024; u += 256) {
        int qn = u >> 7, d = u & 127;
        int rrow = qn * 16 + (d >> 3), cb = (d & 7) * 16;
        const float* p = sF + rrow * 132 + cb;
        float acc = 0.f;
#pragma unroll
        for (int j = 0; j < 16; ++j) acc += p[j];
        g_nodein[((e0 >> 4) + qn) * 128 + d] = acc;
    }
}

__global__ void __launch_bounds__(256, 2)
mpnn_node(const float* __restrict__ nb0, const float* __restrict__ nb1,
          const float* __restrict__ nb2, const float* __restrict__ ng,
          const float* __restrict__ nbeta, float* __restrict__ out, int natoms) {
    extern __shared__ char sm[];
    const uint32_t smb = smem_u32(sm);
    const int t = threadIdx.x, lane = t & 31, w = t >> 5;
    const int wm = w & 3, wn = w >> 2;
    const long r0 = (long)blockIdx.x * 128;
    const int lr = t >> 1, half = t & 1;

    {   // stage A from g_nodein (zero-pad tail rows)
        bool valid = (r0 + lr) < natoms;
        const float* src = g_nodein + (r0 + lr) * 128 + half * 64;
#pragma unroll
        for (int q2 = 0; q2 < 16; ++q2) {
            float4 v = valid ? *reinterpret_cast<const float4*>(src + q2 * 4)
                             : make_float4(0.f, 0.f, 0.f, 0.f);
            uint2 hp, lp;
            split4(v, hp, lp);
            int off = lr * STRB + (half * 64 + q2 * 4) * 2;
            *reinterpret_cast<uint2*>(sm + AH_OFF + off) = hp;
            *reinterpret_cast<uint2*>(sm + AL_OFF + off) = lp;
        }
    }
    __syncthreads();

    float C[2][8][4];
#pragma unroll
    for (int mi = 0; mi < 2; ++mi)
#pragma unroll
        for (int nt = 0; nt < 8; ++nt)
#pragma unroll
            for (int e = 0; e < 4; ++e) C[mi][nt][e] = 0.f;

    mma_layer(C, smb, TB_NW0, 0, lane, wm, wn);
    __syncthreads();
    epi_relu(C, sm, nb0, lane, wm, wn);
    __syncthreads();
    mma_layer(C, smb, TB_NW1, 0, lane, wm, wn);
    __syncthreads();
    epi_relu(C, sm, nb1, lane, wm, wn);
    __syncthreads();
    mma_layer(C, smb, TB_NW2, 0, lane, wm, wn);

    float mu[2][2], rs[2][2];
    ln_stats(C, sm, nb2, t, lane, wm, wn, mu, rs);

    const int grp = lane >> 2, tig = lane & 3;
#pragma unroll
    for (int mi = 0; mi < 2; ++mi)
#pragma unroll
        for (int nt = 0; nt < 8; ++nt) {
            int col0 = wn * 64 + nt * 8 + tig * 2;
            int r1   = wm * 32 + mi * 16 + grp;
            float g0 = __ldg(ng + col0),     g1 = __ldg(ng + col0 + 1);
            float be0 = __ldg(nbeta + col0), be1 = __ldg(nbeta + col0 + 1);
            if (r0 + r1 < natoms) {
                float2 o1 = {(C[mi][nt][0] - mu[mi][0]) * rs[mi][0] * g0 + be0,
                             (C[mi][nt][1] - mu[mi][0]) * rs[mi][0] * g1 + be1};
                *reinterpret_cast<float2*>(out + (r0 + r1) * 128 + col0) = o1;
            }
            if (r0 + r1 + 8 < natoms) {
                float2 o2 = {(C[mi][nt][2] - mu[mi][1]) * rs[mi][1] * g0 + be0,
                             (C[mi][nt][3] - mu[mi][1]) * rs[mi][1] * g1 + be1};
                *reinterpret_cast<float2*>(out + (r0 + r1 + 8) * 128 + col0) = o2;
            }
        }
}

// ============================ launch ========================================
extern "C" void kernel_launch(void* const* d_in, const int* in_sizes, int n_in,
                              void* d_out, int out_size) {
    const float* x         = (const float*)d_in[0];
    const float* edge_attr = (const float*)d_in[1];
    const int*   receivers = (const int*)d_in[2];
    const int*   senders   = (const int*)d_in[3];

    int wi = 4;
    while (wi < n_in && in_sizes[wi] != 3 * 128 * 128) wi++;
    if (wi >= n_in) wi = (in_sizes[4] == 1) ? 5 : 4;

    const float* eW0   = (const float*)d_in[wi + 0];
    const float* eb0   = (const float*)d_in[wi + 1];
    const float* eW1   = (const float*)d_in[wi + 2];
    const float* eb1   = (const float*)d_in[wi + 3];
    const float* eW2   = (const float*)d_in[wi + 4];
    const float* eb2   = (const float*)d_in[wi + 5];
    const float* eg    = (const float*)d_in[wi + 6];
    const float* ebeta = (const float*)d_in[wi + 7];
    const float* nW0   = (const float*)d_in[wi + 8];
    const float* nb0   = (const float*)d_in[wi + 9];
    const float* nW1   = (const float*)d_in[wi + 10];
    const float* nb1   = (const float*)d_in[wi + 11];
    const float* nW2   = (const float*)d_in[wi + 12];
    const float* nb2   = (const float*)d_in[wi + 13];
    const float* ng    = (const float*)d_in[wi + 14];
    const float* nbeta = (const float*)d_in[wi + 15];

    int E      = in_sizes[2];
    int natoms = out_size / 128;

    cudaFuncSetAttribute(mpnn_edge, cudaFuncAttributeMaxDynamicSharedMemorySize, SMEM_TOTAL);
    cudaFuncSetAttribute(mpnn_node, cudaFuncAttributeMaxDynamicSharedMemorySize, SMEM_TOTAL);

    // exactly 5 prep launches so mpnn_edge is launch #6 (ncu -s 5 -c 1 target)
    prep_w <<<192, 256>>>(eW0, 384, TB_EW0);
    prep_w <<<64,  256>>>(eW1, 128, TB_EW1);
    prep_w <<<64,  256>>>(eW2, 128, TB_EW2);
    prep_w <<<64,  256>>>(nW0, 128, TB_NW0);
    prep_w2<<<64,  256>>>(nW1, TB_NW1, nW2, TB_NW2);

    mpnn_edge<<<E / 128, 256, SMEM_TOTAL>>>(x, edge_attr, receivers, senders,
                                            eb0, eb1, eb2, eg, ebeta);
    mpnn_node<<<(natoms + 127) / 128, 256, SMEM_TOTAL>>>(nb0, nb1, nb2, ng, nbeta,
                                                         (float*)d_out, natoms);
}

// round 5
// speedup vs baseline: 3.6004x; 1.0115x over previous
#include <cuda_runtime.h>
#include <cuda_bf16.h>
#include <cstdint>

// ============================================================================
// MPNN on sm_103 (base target — no tcgen05) via warp-level mma.sync m16n8k16
// bf16, split-bf16 3-pass (AhBh + AhBl + AlBh) for fp32-class accuracy.
//   prep (1 launch): weights -> interleaved hi/lo bf16 mma B-fragments
//   edge: CTA=128 edges: gather -> 3-layer MLP -> LN -> local K=16 agg -> g_nodein
//   node: CTA=128 nodes: 3-layer MLP -> LN -> out
// Mainloop is software-pipelined: quarter-step B prefetch + double-buffered A.
// ============================================================================

#define STRB 272                 // A-smem row stride in bytes (136 bf16)
#define AH_OFF 0
#define AL_OFF 34816
#define PS_OFF 69632
#define PQ_OFF 70656
#define MU_OFF 71680
#define RS_OFF 72192
#define SMEM_TOTAL 72704

// B fragments: 1024 tiles (k16 x n8) * 32 lanes * uint4 {bh0,bh1,bl0,bl1}
__device__ __align__(16) uint4 g_B[1024 * 32];
__device__ float g_nodein[20000 * 128];

#define TB_EW0 0
#define TB_EW1 384
#define TB_EW2 512
#define TB_NW0 640
#define TB_NW1 768
#define TB_NW2 896

// ============================ helpers =======================================
__device__ __forceinline__ uint32_t smem_u32(const void* p) {
    uint32_t a;
    asm("{ .reg .u64 t; cvta.to.shared.u64 t, %1; cvt.u32.u64 %0, t; }" : "=r"(a) : "l"(p));
    return a;
}

__device__ __forceinline__ void ldmA(uint32_t addr, uint32_t a[4]) {
    asm volatile("ldmatrix.sync.aligned.m8n8.x4.shared.b16 {%0,%1,%2,%3}, [%4];"
                 : "=r"(a[0]), "=r"(a[1]), "=r"(a[2]), "=r"(a[3]) : "r"(addr));
}

__device__ __forceinline__ void mmabf(float* c, const uint32_t a[4], uint32_t b0, uint32_t b1) {
    asm volatile(
        "mma.sync.aligned.m16n8k16.row.col.f32.bf16.bf16.f32 "
        "{%0,%1,%2,%3}, {%4,%5,%6,%7}, {%8,%9}, {%0,%1,%2,%3};"
        : "+f"(c[0]), "+f"(c[1]), "+f"(c[2]), "+f"(c[3])
        : "r"(a[0]), "r"(a[1]), "r"(a[2]), "r"(a[3]), "r"(b0), "r"(b1));
}

__device__ __forceinline__ void split2(float a, float b, uint32_t& hp, uint32_t& lp) {
    __nv_bfloat162 H = __floats2bfloat162_rn(a, b);
    float ra = a - __bfloat162float(H.x);
    float rb = b - __bfloat162float(H.y);
    __nv_bfloat162 L = __floats2bfloat162_rn(ra, rb);
    hp = *reinterpret_cast<uint32_t*>(&H);
    lp = *reinterpret_cast<uint32_t*>(&L);
}

__device__ __forceinline__ void split4(float4 v, uint2& hp, uint2& lp) {
    split2(v.x, v.y, hp.x, lp.x);
    split2(v.z, v.w, hp.y, lp.y);
}

// stage 64 cols of one row into Ah/Al smem (split bf16)
__device__ __forceinline__ void stageA(char* sm, const float* __restrict__ src,
                                       int lr, int colbase) {
#pragma unroll
    for (int q = 0; q < 16; ++q) {
        float4 v = *reinterpret_cast<const float4*>(src + q * 4);
        uint2 hp, lp;
        split4(v, hp, lp);
        int off = lr * STRB + (colbase + q * 4) * 2;
        *reinterpret_cast<uint2*>(sm + AH_OFF + off) = hp;
        *reinterpret_cast<uint2*>(sm + AL_OFF + off) = lp;
    }
}

// load hi/lo A fragments (ldmatrix x4) for one 16-row k-step
__device__ __forceinline__ void ldA2(uint32_t smb, int wm, int rowoff, int choff, int s,
                                     uint32_t ah[2][4], uint32_t al[2][4]) {
#pragma unroll
    for (int mi = 0; mi < 2; ++mi) {
        uint32_t base = smb + (uint32_t)((wm * 32 + mi * 16 + rowoff) * STRB
                                         + (s * 2 + choff) * 16);
        ldmA(base + AH_OFF, ah[mi]);
        ldmA(base + AL_OFF, al[mi]);
    }
}

// one 128-col K-chunk: 8 k-steps x 4 quarter-steps, software-pipelined.
// Per quarter: prefetch next quarter's 2 B fragments, 12 HMMA on current.
__device__ __forceinline__ void mma_layer(float C[2][8][4], uint32_t smb,
                                          int LB, int soff, int lane, int wm, int wn) {
    const int rowoff = ((lane >> 3) & 1) * 8 + (lane & 7);
    const int choff  = lane >> 4;
    const int tbase  = (LB + soff * 16 + wn * 8) * 32 + lane;   // k-step stride = 512

    uint32_t ah0[2][4], al0[2][4], ah1[2][4], al1[2][4];
    ldA2(smb, wm, rowoff, choff, 0, ah0, al0);

    uint4 bq[2][2];
    bq[0][0] = __ldg(&g_B[tbase]);
    bq[0][1] = __ldg(&g_B[tbase + 32]);

#pragma unroll
    for (int g = 0; g < 32; ++g) {
        const int s = g >> 2, q = g & 3, cur = g & 1;
        if (g < 31) {   // prefetch next quarter's B
            const int ng = g + 1;
            const int tb = tbase + (ng >> 2) * 512 + (ng & 3) * 64;
            bq[cur ^ 1][0] = __ldg(&g_B[tb]);
            bq[cur ^ 1][1] = __ldg(&g_B[tb + 32]);
        }
        if (q == 3 && s < 7) {   // prefetch next k-step's A into alternate buffer
            if (s & 1) ldA2(smb, wm, rowoff, choff, s + 1, ah0, al0);
            else       ldA2(smb, wm, rowoff, choff, s + 1, ah1, al1);
        }
        uint32_t (*ahc)[4] = (s & 1) ? ah1 : ah0;
        uint32_t (*alc)[4] = (s & 1) ? al1 : al0;
#pragma unroll
        for (int mi = 0; mi < 2; ++mi)
#pragma unroll
            for (int f = 0; f < 2; ++f) {
                float* c = C[mi][q * 2 + f];
                mmabf(c, ahc[mi], bq[cur][f].x, bq[cur][f].y);
                mmabf(c, ahc[mi], bq[cur][f].z, bq[cur][f].w);
                mmabf(c, alc[mi], bq[cur][f].x, bq[cur][f].y);
            }
    }
}

// bias + ReLU + split -> rewrite A smem for next layer; zero C
__device__ __forceinline__ void epi_relu(float C[2][8][4], char* sm,
                                         const float* __restrict__ bias,
                                         int lane, int wm, int wn) {
    const int grp = lane >> 2, tig = lane & 3;
#pragma unroll
    for (int mi = 0; mi < 2; ++mi)
#pragma unroll
        for (int nt = 0; nt < 8; ++nt) {
            int col0 = wn * 64 + nt * 8 + tig * 2;
            int row  = wm * 32 + mi * 16 + grp;
            float b0 = __ldg(bias + col0), b1 = __ldg(bias + col0 + 1);
            float v0 = fmaxf(C[mi][nt][0] + b0, 0.f);
            float v1 = fmaxf(C[mi][nt][1] + b1, 0.f);
            float v2 = fmaxf(C[mi][nt][2] + b0, 0.f);
            float v3 = fmaxf(C[mi][nt][3] + b1, 0.f);
            uint32_t h, l;
            split2(v0, v1, h, l);
            *reinterpret_cast<uint32_t*>(sm + AH_OFF + row * STRB + col0 * 2) = h;
            *reinterpret_cast<uint32_t*>(sm + AL_OFF + row * STRB + col0 * 2) = l;
            split2(v2, v3, h, l);
            *reinterpret_cast<uint32_t*>(sm + AH_OFF + (row + 8) * STRB + col0 * 2) = h;
            *reinterpret_cast<uint32_t*>(sm + AL_OFF + (row + 8) * STRB + col0 * 2) = l;
            C[mi][nt][0] = C[mi][nt][1] = C[mi][nt][2] = C[mi][nt][3] = 0.f;
        }
}

// add bias in place, compute per-row LN stats (mu, rs) for this lane's 4 rows
__device__ __forceinline__ void ln_stats(float C[2][8][4], char* sm,
                                         const float* __restrict__ bias,
                                         int t, int lane, int wm, int wn,
                                         float mu[2][2], float rs[2][2]) {
    const int grp = lane >> 2, tig = lane & 3;
    float s[2][2] = {{0.f, 0.f}, {0.f, 0.f}};
    float q[2][2] = {{0.f, 0.f}, {0.f, 0.f}};
#pragma unroll
    for (int mi = 0; mi < 2; ++mi)
#pragma unroll
        for (int nt = 0; nt < 8; ++nt) {
            int col0 = wn * 64 + nt * 8 + tig * 2;
            float b0 = __ldg(bias + col0), b1 = __ldg(bias + col0 + 1);
            C[mi][nt][0] += b0; C[mi][nt][1] += b1;
            C[mi][nt][2] += b0; C[mi][nt][3] += b1;
            s[mi][0] += C[mi][nt][0] + C[mi][nt][1];
            q[mi][0] += C[mi][nt][0] * C[mi][nt][0] + C[mi][nt][1] * C[mi][nt][1];
            s[mi][1] += C[mi][nt][2] + C[mi][nt][3];
            q[mi][1] += C[mi][nt][2] * C[mi][nt][2] + C[mi][nt][3] * C[mi][nt][3];
        }
#pragma unroll
    for (int off = 1; off <= 2; off <<= 1)
#pragma unroll
        for (int mi = 0; mi < 2; ++mi)
#pragma unroll
            for (int h = 0; h < 2; ++h) {
                s[mi][h] += __shfl_xor_sync(0xffffffffu, s[mi][h], off);
                q[mi][h] += __shfl_xor_sync(0xffffffffu, q[mi][h], off);
            }
    float* ps = reinterpret_cast<float*>(sm + PS_OFF);
    float* pq = reinterpret_cast<float*>(sm + PQ_OFF);
    if (tig == 0) {
#pragma unroll
        for (int mi = 0; mi < 2; ++mi)
#pragma unroll
            for (int h = 0; h < 2; ++h) {
                int row = wm * 32 + mi * 16 + grp + h * 8;
                ps[wn * 128 + row] = s[mi][h];
                pq[wn * 128 + row] = q[mi][h];
            }
    }
    __syncthreads();
    float* smu = reinterpret_cast<float*>(sm + MU_OFF);
    float* srs = reinterpret_cast<float*>(sm + RS_OFF);
    if (t < 128) {
        float su = ps[t] + ps[128 + t];
        float sq = pq[t] + pq[128 + t];
        float m  = su * (1.f / 128.f);
        float v  = sq * (1.f / 128.f) - m * m;
        smu[t] = m;
        srs[t] = rsqrtf(v + 1e-5f);
    }
    __syncthreads();
#pragma unroll
    for (int mi = 0; mi < 2; ++mi)
#pragma unroll
        for (int h = 0; h < 2; ++h) {
            int row = wm * 32 + mi * 16 + grp + h * 8;
            mu[mi][h] = smu[row];
            rs[mi][h] = srs[row];
        }
}

// ============================ prep ==========================================
__device__ __forceinline__ void prep_one(const float* __restrict__ W, int idx, int tileBase) {
    int k = idx >> 7, n = idx & 127;
    float wv = W[idx];
    __nv_bfloat16 h = __float2bfloat16(wv);
    __nv_bfloat16 l = __float2bfloat16(wv - __bfloat162float(h));
    int klocal = k & 15;
    int tile = tileBase + (k >> 4) * 16 + (n >> 3);
    int lane = (n & 7) * 4 + ((klocal >> 1) & 3);
    int reg  = (klocal >> 3) & 1;
    int half = klocal & 1;
    unsigned short* gb = reinterpret_cast<unsigned short*>(g_B);
    int base = (tile * 32 + lane) * 8;
    gb[base + reg * 2 + half]     = *reinterpret_cast<unsigned short*>(&h);
    gb[base + 4 + reg * 2 + half] = *reinterpret_cast<unsigned short*>(&l);
}

__global__ void prep_all(const float* __restrict__ eW0, const float* __restrict__ eW1,
                         const float* __restrict__ eW2, const float* __restrict__ nW0,
                         const float* __restrict__ nW1, const float* __restrict__ nW2) {
    int idx = blockIdx.x * 256 + threadIdx.x;    // grid covers 131072
    if (idx < 49152) { prep_one(eW0, idx, TB_EW0); return; }
    int r = idx - 49152;
    int li = r & 16383;
    switch (r >> 14) {
        case 0: prep_one(eW1, li, TB_EW1); break;
        case 1: prep_one(eW2, li, TB_EW2); break;
        case 2: prep_one(nW0, li, TB_NW0); break;
        case 3: prep_one(nW1, li, TB_NW1); break;
        default: prep_one(nW2, li, TB_NW2); break;
    }
}

// ============================ kernels =======================================
__global__ void __launch_bounds__(256, 2)
mpnn_edge(const float* __restrict__ x, const float* __restrict__ eattr,
          const int* __restrict__ recv, const int* __restrict__ send,
          const float* __restrict__ eb0, const float* __restrict__ eb1,
          const float* __restrict__ eb2, const float* __restrict__ eg,
          const float* __restrict__ ebeta) {
    extern __shared__ char sm[];
    const uint32_t smb = smem_u32(sm);
    const int t = threadIdx.x, lane = t & 31, w = t >> 5;
    const int wm = w & 3, wn = w >> 2;
    const long e0 = (long)blockIdx.x * 128;
    const int lr = t >> 1, half = t & 1;
    const long re = (long)__ldg(recv + e0 + lr) * 128;
    const long se = (long)__ldg(send + e0 + lr) * 128;

    float C[2][8][4];
#pragma unroll
    for (int mi = 0; mi < 2; ++mi)
#pragma unroll
        for (int nt = 0; nt < 8; ++nt)
#pragma unroll
            for (int e = 0; e < 4; ++e) C[mi][nt][e] = 0.f;

    // ------- layer 0: K=384, three 128-col chunks -------
#pragma unroll 1
    for (int c = 0; c < 3; ++c) {
        const float* src = (c == 0) ? x + re
                         : (c == 1) ? x + se
                                    : eattr + (e0 + lr) * 128;
        stageA(sm, src + half * 64, lr, half * 64);
        __syncthreads();
        mma_layer(C, smb, TB_EW0, c * 8, lane, wm, wn);
        __syncthreads();
    }
    epi_relu(C, sm, eb0, lane, wm, wn);
    __syncthreads();
    mma_layer(C, smb, TB_EW1, 0, lane, wm, wn);
    __syncthreads();
    epi_relu(C, sm, eb1, lane, wm, wn);
    __syncthreads();
    mma_layer(C, smb, TB_EW2, 0, lane, wm, wn);

    float mu[2][2], rs[2][2];
    ln_stats(C, sm, eb2, t, lane, wm, wn, mu, rs);

    // LN-apply (with eg/ebeta) into fp32 smem buffer (reuses A region)
    float* sF = reinterpret_cast<float*>(sm);
    const int grp = lane >> 2, tig = lane & 3;
#pragma unroll
    for (int mi = 0; mi < 2; ++mi)
#pragma unroll
        for (int nt = 0; nt < 8; ++nt) {
            int col0 = wn * 64 + nt * 8 + tig * 2;
            int r1   = wm * 32 + mi * 16 + grp;
            float g0 = __ldg(eg + col0),    g1 = __ldg(eg + col0 + 1);
            float be0 = __ldg(ebeta + col0), be1 = __ldg(ebeta + col0 + 1);
            float2 o1 = {(C[mi][nt][0] - mu[mi][0]) * rs[mi][0] * g0 + be0,
                         (C[mi][nt][1] - mu[mi][0]) * rs[mi][0] * g1 + be1};
            float2 o2 = {(C[mi][nt][2] - mu[mi][1]) * rs[mi][1] * g0 + be0,
                         (C[mi][nt][3] - mu[mi][1]) * rs[mi][1] * g1 + be1};
            *reinterpret_cast<float2*>(sF + r1 * 132 + col0)       = o1;
            *reinterpret_cast<float2*>(sF + (r1 + 8) * 132 + col0) = o2;
        }
    __syncthreads();

    // block-local aggregation: node_in[q][d] = sum_j m[q*16 + d/8][(d%8)*16 + j]
#pragma unroll
    for (int u = t; u < 1024; u += 256) {
        int qn = u >> 7, d = u & 127;
        int rrow = qn * 16 + (d >> 3), cb = (d & 7) * 16;
        const float* p = sF + rrow * 132 + cb;
        float acc = 0.f;
#pragma unroll
        for (int j = 0; j < 16; ++j) acc += p[j];
        g_nodein[((e0 >> 4) + qn) * 128 + d] = acc;
    }
}

__global__ void __launch_bounds__(256, 2)
mpnn_node(const float* __restrict__ nb0, const float* __restrict__ nb1,
          const float* __restrict__ nb2, const float* __restrict__ ng,
          const float* __restrict__ nbeta, float* __restrict__ out, int natoms) {
    extern __shared__ char sm[];
    const uint32_t smb = smem_u32(sm);
    const int t = threadIdx.x, lane = t & 31, w = t >> 5;
    const int wm = w & 3, wn = w >> 2;
    const long r0 = (long)blockIdx.x * 128;
    const int lr = t >> 1, half = t & 1;

    {   // stage A from g_nodein (zero-pad tail rows)
        bool valid = (r0 + lr) < natoms;
        const float* src = g_nodein + (r0 + lr) * 128 + half * 64;
#pragma unroll
        for (int q2 = 0; q2 < 16; ++q2) {
            float4 v = valid ? *reinterpret_cast<const float4*>(src + q2 * 4)
                             : make_float4(0.f, 0.f, 0.f, 0.f);
            uint2 hp, lp;
            split4(v, hp, lp);
            int off = lr * STRB + (half * 64 + q2 * 4) * 2;
            *reinterpret_cast<uint2*>(sm + AH_OFF + off) = hp;
            *reinterpret_cast<uint2*>(sm + AL_OFF + off) = lp;
        }
    }
    __syncthreads();

    float C[2][8][4];
#pragma unroll
    for (int mi = 0; mi < 2; ++mi)
#pragma unroll
        for (int nt = 0; nt < 8; ++nt)
#pragma unroll
            for (int e = 0; e < 4; ++e) C[mi][nt][e] = 0.f;

    mma_layer(C, smb, TB_NW0, 0, lane, wm, wn);
    __syncthreads();
    epi_relu(C, sm, nb0, lane, wm, wn);
    __syncthreads();
    mma_layer(C, smb, TB_NW1, 0, lane, wm, wn);
    __syncthreads();
    epi_relu(C, sm, nb1, lane, wm, wn);
    __syncthreads();
    mma_layer(C, smb, TB_NW2, 0, lane, wm, wn);

    float mu[2][2], rs[2][2];
    ln_stats(C, sm, nb2, t, lane, wm, wn, mu, rs);

    const int grp = lane >> 2, tig = lane & 3;
#pragma unroll
    for (int mi = 0; mi < 2; ++mi)
#pragma unroll
        for (int nt = 0; nt < 8; ++nt) {
            int col0 = wn * 64 + nt * 8 + tig * 2;
            int r1   = wm * 32 + mi * 16 + grp;
            float g0 = __ldg(ng + col0),     g1 = __ldg(ng + col0 + 1);
            float be0 = __ldg(nbeta + col0), be1 = __ldg(nbeta + col0 + 1);
            if (r0 + r1 < natoms) {
                float2 o1 = {(C[mi][nt][0] - mu[mi][0]) * rs[mi][0] * g0 + be0,
                             (C[mi][nt][1] - mu[mi][0]) * rs[mi][0] * g1 + be1};
                *reinterpret_cast<float2*>(out + (r0 + r1) * 128 + col0) = o1;
            }
            if (r0 + r1 + 8 < natoms) {
                float2 o2 = {(C[mi][nt][2] - mu[mi][1]) * rs[mi][1] * g0 + be0,
                             (C[mi][nt][3] - mu[mi][1]) * rs[mi][1] * g1 + be1};
                *reinterpret_cast<float2*>(out + (r0 + r1 + 8) * 128 + col0) = o2;
            }
        }
}

// ============================ launch ========================================
extern "C" void kernel_launch(void* const* d_in, const int* in_sizes, int n_in,
                              void* d_out, int out_size) {
    const float* x         = (const float*)d_in[0];
    const float* edge_attr = (const float*)d_in[1];
    const int*   receivers = (const int*)d_in[2];
    const int*   senders   = (const int*)d_in[3];

    int wi = 4;
    while (wi < n_in && in_sizes[wi] != 3 * 128 * 128) wi++;
    if (wi >= n_in) wi = (in_sizes[4] == 1) ? 5 : 4;

    const float* eW0   = (const float*)d_in[wi + 0];
    const float* eb0   = (const float*)d_in[wi + 1];
    const float* eW1   = (const float*)d_in[wi + 2];
    const float* eb1   = (const float*)d_in[wi + 3];
    const float* eW2   = (const float*)d_in[wi + 4];
    const float* eb2   = (const float*)d_in[wi + 5];
    const float* eg    = (const float*)d_in[wi + 6];
    const float* ebeta = (const float*)d_in[wi + 7];
    const float* nW0   = (const float*)d_in[wi + 8];
    const float* nb0   = (const float*)d_in[wi + 9];
    const float* nW1   = (const float*)d_in[wi + 10];
    const float* nb1   = (const float*)d_in[wi + 11];
    const float* nW2   = (const float*)d_in[wi + 12];
    const float* nb2   = (const float*)d_in[wi + 13];
    const float* ng    = (const float*)d_in[wi + 14];
    const float* nbeta = (const float*)d_in[wi + 15];

    int E      = in_sizes[2];
    int natoms = out_size / 128;

    cudaFuncSetAttribute(mpnn_edge, cudaFuncAttributeMaxDynamicSharedMemorySize, SMEM_TOTAL);
    cudaFuncSetAttribute(mpnn_node, cudaFuncAttributeMaxDynamicSharedMemorySize, SMEM_TOTAL);

    prep_all<<<512, 256>>>(eW0, eW1, eW2, nW0, nW1, nW2);
    mpnn_edge<<<E / 128, 256, SMEM_TOTAL>>>(x, edge_attr, receivers, senders,
                                            eb0, eb1, eb2, eg, ebeta);
    mpnn_node<<<(natoms + 127) / 128, 256, SMEM_TOTAL>>>(nb0, nb1, nb2, ng, nbeta,
                                                         (float*)d_out, natoms);
}

// round 6
// speedup vs baseline: 4.9373x; 1.3713x over previous
#include <cuda_runtime.h>
#include <cuda_fp16.h>
#include <cstdint>

// ============================================================================
// MPNN on sm_103 (base target — no tcgen05) via warp-level mma.sync m16n8k16
// fp16, 2-pass split-B (A·Bh + A·Bl with B = Bh + Bl exact fp16 split).
//   prep (1 launch): weights -> interleaved hi/lo fp16 mma B-fragments
//   edge: CTA=128 edges: gather -> 3-layer MLP -> LN -> quad-shuffle K=16 agg
//   node: CTA=128 nodes: 3-layer MLP -> LN -> out
// ============================================================================

#define STRB 272                 // A-smem row stride in bytes (136 fp16)
#define AH_OFF 0
#define PS_OFF 34816
#define PQ_OFF 35840
#define MU_OFF 36864
#define RS_OFF 37376
#define SMEM_TOTAL 37888

// B fragments: 1024 tiles (k16 x n8) * 32 lanes * uint4 {bh0,bh1,bl0,bl1}
__device__ __align__(16) uint4 g_B[1024 * 32];
__device__ float g_nodein[20000 * 128];

#define TB_EW0 0
#define TB_EW1 384
#define TB_EW2 512
#define TB_NW0 640
#define TB_NW1 768
#define TB_NW2 896

// ============================ helpers =======================================
__device__ __forceinline__ uint32_t smem_u32(const void* p) {
    uint32_t a;
    asm("{ .reg .u64 t; cvta.to.shared.u64 t, %1; cvt.u32.u64 %0, t; }" : "=r"(a) : "l"(p));
    return a;
}

__device__ __forceinline__ void ldmA(uint32_t addr, uint32_t a[4]) {
    asm volatile("ldmatrix.sync.aligned.m8n8.x4.shared.b16 {%0,%1,%2,%3}, [%4];"
                 : "=r"(a[0]), "=r"(a[1]), "=r"(a[2]), "=r"(a[3]) : "r"(addr));
}

__device__ __forceinline__ void mmah(float* c, const uint32_t a[4], uint32_t b0, uint32_t b1) {
    asm volatile(
        "mma.sync.aligned.m16n8k16.row.col.f32.f16.f16.f32 "
        "{%0,%1,%2,%3}, {%4,%5,%6,%7}, {%8,%9}, {%0,%1,%2,%3};"
        : "+f"(c[0]), "+f"(c[1]), "+f"(c[2]), "+f"(c[3])
        : "r"(a[0]), "r"(a[1]), "r"(a[2]), "r"(a[3]), "r"(b0), "r"(b1));
}

__device__ __forceinline__ uint32_t packh2(float a, float b) {
    __half2 h = __floats2half2_rn(a, b);
    return *reinterpret_cast<uint32_t*>(&h);
}

// stage 64 cols of one row into A smem (fp16)
__device__ __forceinline__ void stageA(char* sm, const float* __restrict__ src,
                                       int lr, int colbase) {
#pragma unroll
    for (int q = 0; q < 16; ++q) {
        float4 v = *reinterpret_cast<const float4*>(src + q * 4);
        uint2 hp;
        hp.x = packh2(v.x, v.y);
        hp.y = packh2(v.z, v.w);
        int off = lr * STRB + (colbase + q * 4) * 2;
        *reinterpret_cast<uint2*>(sm + AH_OFF + off) = hp;
    }
}

// load A fragments (ldmatrix x4) for one 16-row k-step
__device__ __forceinline__ void ldA1(uint32_t smb, int wm, int rowoff, int choff, int s,
                                     uint32_t ah[2][4]) {
#pragma unroll
    for (int mi = 0; mi < 2; ++mi) {
        uint32_t base = smb + (uint32_t)((wm * 32 + mi * 16 + rowoff) * STRB
                                         + (s * 2 + choff) * 16);
        ldmA(base + AH_OFF, ah[mi]);
    }
}

// one 128-col K-chunk: 8 k-steps x 4 quarter-steps, software-pipelined.
// Per quarter: prefetch next quarter's 2 B fragments, 8 HMMA on current.
__device__ __forceinline__ void mma_layer(float C[2][8][4], uint32_t smb,
                                          int LB, int soff, int lane, int wm, int wn) {
    const int rowoff = ((lane >> 3) & 1) * 8 + (lane & 7);
    const int choff  = lane >> 4;
    const int tbase  = (LB + soff * 16 + wn * 8) * 32 + lane;   // k-step stride = 512

    uint32_t ah0[2][4], ah1[2][4];
    ldA1(smb, wm, rowoff, choff, 0, ah0);

    uint4 bq[2][2];
    bq[0][0] = __ldg(&g_B[tbase]);
    bq[0][1] = __ldg(&g_B[tbase + 32]);

#pragma unroll
    for (int g = 0; g < 32; ++g) {
        const int s = g >> 2, q = g & 3, cur = g & 1;
        if (g < 31) {   // prefetch next quarter's B
            const int ng = g + 1;
            const int tb = tbase + (ng >> 2) * 512 + (ng & 3) * 64;
            bq[cur ^ 1][0] = __ldg(&g_B[tb]);
            bq[cur ^ 1][1] = __ldg(&g_B[tb + 32]);
        }
        if (q == 3 && s < 7) {   // prefetch next k-step's A into alternate buffer
            if (s & 1) ldA1(smb, wm, rowoff, choff, s + 1, ah0);
            else       ldA1(smb, wm, rowoff, choff, s + 1, ah1);
        }
        uint32_t (*ahc)[4] = (s & 1) ? ah1 : ah0;
#pragma unroll
        for (int mi = 0; mi < 2; ++mi)
#pragma unroll
            for (int f = 0; f < 2; ++f) {
                float* c = C[mi][q * 2 + f];
                mmah(c, ahc[mi], bq[cur][f].x, bq[cur][f].y);   // A·Bh
                mmah(c, ahc[mi], bq[cur][f].z, bq[cur][f].w);   // A·Bl
            }
    }
}

// bias + ReLU -> rewrite A smem (fp16) for next layer; zero C
__device__ __forceinline__ void epi_relu(float C[2][8][4], char* sm,
                                         const float* __restrict__ bias,
                                         int lane, int wm, int wn) {
    const int grp = lane >> 2, tig = lane & 3;
#pragma unroll
    for (int mi = 0; mi < 2; ++mi)
#pragma unroll
        for (int nt = 0; nt < 8; ++nt) {
            int col0 = wn * 64 + nt * 8 + tig * 2;
            int row  = wm * 32 + mi * 16 + grp;
            float b0 = __ldg(bias + col0), b1 = __ldg(bias + col0 + 1);
            float v0 = fmaxf(C[mi][nt][0] + b0, 0.f);
            float v1 = fmaxf(C[mi][nt][1] + b1, 0.f);
            float v2 = fmaxf(C[mi][nt][2] + b0, 0.f);
            float v3 = fmaxf(C[mi][nt][3] + b1, 0.f);
            *reinterpret_cast<uint32_t*>(sm + AH_OFF + row * STRB + col0 * 2) = packh2(v0, v1);
            *reinterpret_cast<uint32_t*>(sm + AH_OFF + (row + 8) * STRB + col0 * 2) = packh2(v2, v3);
            C[mi][nt][0] = C[mi][nt][1] = C[mi][nt][2] = C[mi][nt][3] = 0.f;
        }
}

// add bias in place, compute per-row LN stats (mu, rs) for this lane's 4 rows
__device__ __forceinline__ void ln_stats(float C[2][8][4], char* sm,
                                         const float* __restrict__ bias,
                                         int t, int lane, int wm, int wn,
                                         float mu[2][2], float rs[2][2]) {
    const int grp = lane >> 2, tig = lane & 3;
    float s[2][2] = {{0.f, 0.f}, {0.f, 0.f}};
    float q[2][2] = {{0.f, 0.f}, {0.f, 0.f}};
#pragma unroll
    for (int mi = 0; mi < 2; ++mi)
#pragma unroll
        for (int nt = 0; nt < 8; ++nt) {
            int col0 = wn * 64 + nt * 8 + tig * 2;
            float b0 = __ldg(bias + col0), b1 = __ldg(bias + col0 + 1);
            C[mi][nt][0] += b0; C[mi][nt][1] += b1;
            C[mi][nt][2] += b0; C[mi][nt][3] += b1;
            s[mi][0] += C[mi][nt][0] + C[mi][nt][1];
            q[mi][0] += C[mi][nt][0] * C[mi][nt][0] + C[mi][nt][1] * C[mi][nt][1];
            s[mi][1] += C[mi][nt][2] + C[mi][nt][3];
            q[mi][1] += C[mi][nt][2] * C[mi][nt][2] + C[mi][nt][3] * C[mi][nt][3];
        }
#pragma unroll
    for (int off = 1; off <= 2; off <<= 1)
#pragma unroll
        for (int mi = 0; mi < 2; ++mi)
#pragma unroll
            for (int h = 0; h < 2; ++h) {
                s[mi][h] += __shfl_xor_sync(0xffffffffu, s[mi][h], off);
                q[mi][h] += __shfl_xor_sync(0xffffffffu, q[mi][h], off);
            }
    float* ps = reinterpret_cast<float*>(sm + PS_OFF);
    float* pq = reinterpret_cast<float*>(sm + PQ_OFF);
    if (tig == 0) {
#pragma unroll
        for (int mi = 0; mi < 2; ++mi)
#pragma unroll
            for (int h = 0; h < 2; ++h) {
                int row = wm * 32 + mi * 16 + grp + h * 8;
                ps[wn * 128 + row] = s[mi][h];
                pq[wn * 128 + row] = q[mi][h];
            }
    }
    __syncthreads();
    float* smu = reinterpret_cast<float*>(sm + MU_OFF);
    float* srs = reinterpret_cast<float*>(sm + RS_OFF);
    if (t < 128) {
        float su = ps[t] + ps[128 + t];
        float sq = pq[t] + pq[128 + t];
        float m  = su * (1.f / 128.f);
        float v  = sq * (1.f / 128.f) - m * m;
        smu[t] = m;
        srs[t] = rsqrtf(v + 1e-5f);
    }
    __syncthreads();
#pragma unroll
    for (int mi = 0; mi < 2; ++mi)
#pragma unroll
        for (int h = 0; h < 2; ++h) {
            int row = wm * 32 + mi * 16 + grp + h * 8;
            mu[mi][h] = smu[row];
            rs[mi][h] = srs[row];
        }
}

// ============================ prep ==========================================
__device__ __forceinline__ void prep_one(const float* __restrict__ W, int idx, int tileBase) {
    int k = idx >> 7, n = idx & 127;
    float wv = W[idx];
    __half h = __float2half_rn(wv);
    __half l = __float2half_rn(wv - __half2float(h));
    int klocal = k & 15;
    int tile = tileBase + (k >> 4) * 16 + (n >> 3);
    int lane = (n & 7) * 4 + ((klocal >> 1) & 3);
    int reg  = (klocal >> 3) & 1;
    int half = klocal & 1;
    unsigned short* gb = reinterpret_cast<unsigned short*>(g_B);
    int base = (tile * 32 + lane) * 8;
    gb[base + reg * 2 + half]     = *reinterpret_cast<unsigned short*>(&h);
    gb[base + 4 + reg * 2 + half] = *reinterpret_cast<unsigned short*>(&l);
}

__global__ void prep_all(const float* __restrict__ eW0, const float* __restrict__ eW1,
                         const float* __restrict__ eW2, const float* __restrict__ nW0,
                         const float* __restrict__ nW1, const float* __restrict__ nW2) {
    int idx = blockIdx.x * 256 + threadIdx.x;    // grid covers 131072
    if (idx < 49152) { prep_one(eW0, idx, TB_EW0); return; }
    int r = idx - 49152;
    int li = r & 16383;
    switch (r >> 14) {
        case 0: prep_one(eW1, li, TB_EW1); break;
        case 1: prep_one(eW2, li, TB_EW2); break;
        case 2: prep_one(nW0, li, TB_NW0); break;
        case 3: prep_one(nW1, li, TB_NW1); break;
        default: prep_one(nW2, li, TB_NW2); break;
    }
}

// ============================ kernels =======================================
__global__ void __launch_bounds__(256, 2)
mpnn_edge(const float* __restrict__ x, const float* __restrict__ eattr,
          const int* __restrict__ recv, const int* __restrict__ send,
          const float* __restrict__ eb0, const float* __restrict__ eb1,
          const float* __restrict__ eb2, const float* __restrict__ eg,
          const float* __restrict__ ebeta) {
    extern __shared__ char sm[];
    const uint32_t smb = smem_u32(sm);
    const int t = threadIdx.x, lane = t & 31, w = t >> 5;
    const int wm = w & 3, wn = w >> 2;
    const long e0 = (long)blockIdx.x * 128;
    const int lr = t >> 1, half = t & 1;
    const long re = (long)__ldg(recv + e0 + lr) * 128;
    const long se = (long)__ldg(send + e0 + lr) * 128;

    float C[2][8][4];
#pragma unroll
    for (int mi = 0; mi < 2; ++mi)
#pragma unroll
        for (int nt = 0; nt < 8; ++nt)
#pragma unroll
            for (int e = 0; e < 4; ++e) C[mi][nt][e] = 0.f;

    // ------- layer 0: K=384, three 128-col chunks -------
#pragma unroll 1
    for (int c = 0; c < 3; ++c) {
        const float* src = (c == 0) ? x + re
                         : (c == 1) ? x + se
                                    : eattr + (e0 + lr) * 128;
        stageA(sm, src + half * 64, lr, half * 64);
        __syncthreads();
        mma_layer(C, smb, TB_EW0, c * 8, lane, wm, wn);
        __syncthreads();
    }
    epi_relu(C, sm, eb0, lane, wm, wn);
    __syncthreads();
    mma_layer(C, smb, TB_EW1, 0, lane, wm, wn);
    __syncthreads();
    epi_relu(C, sm, eb1, lane, wm, wn);
    __syncthreads();
    mma_layer(C, smb, TB_EW2, 0, lane, wm, wn);

    float mu[2][2], rs[2][2];
    ln_stats(C, sm, eb2, t, lane, wm, wn, mu, rs);

    // LN-apply + block-local K=16 aggregation entirely in registers.
    // node_in[n][i] = sum_{j<16} m[n*16 + i/8][(i%8)*16 + j]; a 16-consecutive-
    // column group lives in nt pair {2g,2g+1} across the 4 lanes of a quad.
    const int grp = lane >> 2, tig = lane & 3;
#pragma unroll
    for (int mi = 0; mi < 2; ++mi)
#pragma unroll
        for (int h = 0; h < 2; ++h) {
            float part[4];
#pragma unroll
            for (int g = 0; g < 4; ++g) {
                float acc = 0.f;
#pragma unroll
                for (int u = 0; u < 2; ++u) {
                    int nt = g * 2 + u;
                    int col0 = wn * 64 + nt * 8 + tig * 2;
                    float g0 = __ldg(eg + col0),     g1 = __ldg(eg + col0 + 1);
                    float b0 = __ldg(ebeta + col0),  b1 = __ldg(ebeta + col0 + 1);
                    acc += (C[mi][nt][h * 2 + 0] - mu[mi][h]) * rs[mi][h] * g0 + b0;
                    acc += (C[mi][nt][h * 2 + 1] - mu[mi][h]) * rs[mi][h] * g1 + b1;
                }
                part[g] = acc;
            }
#pragma unroll
            for (int g = 0; g < 4; ++g) {
                part[g] += __shfl_xor_sync(0xffffffffu, part[g], 1);
                part[g] += __shfl_xor_sync(0xffffffffu, part[g], 2);
            }
            int row = wm * 32 + mi * 16 + grp + h * 8;
            int i   = (row & 15) * 8 + wn * 4 + tig;
            g_nodein[((e0 >> 4) + (row >> 4)) * 128 + i] = part[tig];
        }
}

__global__ void __launch_bounds__(256, 2)
mpnn_node(const float* __restrict__ nb0, const float* __restrict__ nb1,
          const float* __restrict__ nb2, const float* __restrict__ ng,
          const float* __restrict__ nbeta, float* __restrict__ out, int natoms) {
    extern __shared__ char sm[];
    const uint32_t smb = smem_u32(sm);
    const int t = threadIdx.x, lane = t & 31, w = t >> 5;
    const int wm = w & 3, wn = w >> 2;
    const long r0 = (long)blockIdx.x * 128;
    const int lr = t >> 1, half = t & 1;

    {   // stage A from g_nodein (zero-pad tail rows)
        bool valid = (r0 + lr) < natoms;
        const float* src = g_nodein + (r0 + lr) * 128 + half * 64;
#pragma unroll
        for (int q2 = 0; q2 < 16; ++q2) {
            float4 v = valid ? *reinterpret_cast<const float4*>(src + q2 * 4)
                             : make_float4(0.f, 0.f, 0.f, 0.f);
            uint2 hp;
            hp.x = packh2(v.x, v.y);
            hp.y = packh2(v.z, v.w);
            int off = lr * STRB + (half * 64 + q2 * 4) * 2;
            *reinterpret_cast<uint2*>(sm + AH_OFF + off) = hp;
        }
    }
    __syncthreads();

    float C[2][8][4];
#pragma unroll
    for (int mi = 0; mi < 2; ++mi)
#pragma unroll
        for (int nt = 0; nt < 8; ++nt)
#pragma unroll
            for (int e = 0; e < 4; ++e) C[mi][nt][e] = 0.f;

    mma_layer(C, smb, TB_NW0, 0, lane, wm, wn);
    __syncthreads();
    epi_relu(C, sm, nb0, lane, wm, wn);
    __syncthreads();
    mma_layer(C, smb, TB_NW1, 0, lane, wm, wn);
    __syncthreads();
    epi_relu(C, sm, nb1, lane, wm, wn);
    __syncthreads();
    mma_layer(C, smb, TB_NW2, 0, lane, wm, wn);

    float mu[2][2], rs[2][2];
    ln_stats(C, sm, nb2, t, lane, wm, wn, mu, rs);

    const int grp = lane >> 2, tig = lane & 3;
#pragma unroll
    for (int mi = 0; mi < 2; ++mi)
#pragma unroll
        for (int nt = 0; nt < 8; ++nt) {
            int col0 = wn * 64 + nt * 8 + tig * 2;
            int r1   = wm * 32 + mi * 16 + grp;
            float g0 = __ldg(ng + col0),     g1 = __ldg(ng + col0 + 1);
            float be0 = __ldg(nbeta + col0), be1 = __ldg(nbeta + col0 + 1);
            if (r0 + r1 < natoms) {
                float2 o1 = {(C[mi][nt][0] - mu[mi][0]) * rs[mi][0] * g0 + be0,
                             (C[mi][nt][1] - mu[mi][0]) * rs[mi][0] * g1 + be1};
                *reinterpret_cast<float2*>(out + (r0 + r1) * 128 + col0) = o1;
            }
            if (r0 + r1 + 8 < natoms) {
                float2 o2 = {(C[mi][nt][2] - mu[mi][1]) * rs[mi][1] * g0 + be0,
                             (C[mi][nt][3] - mu[mi][1]) * rs[mi][1] * g1 + be1};
                *reinterpret_cast<float2*>(out + (r0 + r1 + 8) * 128 + col0) = o2;
            }
        }
}

// ============================ launch ========================================
extern "C" void kernel_launch(void* const* d_in, const int* in_sizes, int n_in,
                              void* d_out, int out_size) {
    const float* x         = (const float*)d_in[0];
    const float* edge_attr = (const float*)d_in[1];
    const int*   receivers = (const int*)d_in[2];
    const int*   senders   = (const int*)d_in[3];

    int wi = 4;
    while (wi < n_in && in_sizes[wi] != 3 * 128 * 128) wi++;
    if (wi >= n_in) wi = (in_sizes[4] == 1) ? 5 : 4;

    const float* eW0   = (const float*)d_in[wi + 0];
    const float* eb0   = (const float*)d_in[wi + 1];
    const float* eW1   = (const float*)d_in[wi + 2];
    const float* eb1   = (const float*)d_in[wi + 3];
    const float* eW2   = (const float*)d_in[wi + 4];
    const float* eb2   = (const float*)d_in[wi + 5];
    const float* eg    = (const float*)d_in[wi + 6];
    const float* ebeta = (const float*)d_in[wi + 7];
    const float* nW0   = (const float*)d_in[wi + 8];
    const float* nb0   = (const float*)d_in[wi + 9];
    const float* nW1   = (const float*)d_in[wi + 10];
    const float* nb1   = (const float*)d_in[wi + 11];
    const float* nW2   = (const float*)d_in[wi + 12];
    const float* nb2   = (const float*)d_in[wi + 13];
    const float* ng    = (const float*)d_in[wi + 14];
    const float* nbeta = (const float*)d_in[wi + 15];

    int E      = in_sizes[2];
    int natoms = out_size / 128;

    prep_all<<<512, 256>>>(eW0, eW1, eW2, nW0, nW1, nW2);
    mpnn_edge<<<E / 128, 256, SMEM_TOTAL>>>(x, edge_attr, receivers, senders,
                                            eb0, eb1, eb2, eg, ebeta);
    mpnn_node<<<(natoms + 127) / 128, 256, SMEM_TOTAL>>>(nb0, nb1, nb2, ng, nbeta,
                                                         (float*)d_out, natoms);
}